// round 11
// baseline (speedup 1.0000x reference)
#include <cuda_runtime.h>
#include <cuda_bf16.h>
#include <cstdint>
#include <math.h>

#define BATCH 8
#define NQ    1024
#define NKV   4096
#define DIM   512

// ---------------- scratch (device globals: allocation-free) ----------------
__device__ __align__(16) __nv_bfloat16 s_ph [BATCH*NQ*DIM],  s_pl [BATCH*NQ*DIM];   // prototype split
__device__ __align__(16) __nv_bfloat16 s_xh [BATCH*NKV*DIM], s_xl [BATCH*NKV*DIM];  // compacted q_x split
__device__ __align__(16) __nv_bfloat16 s_wqh[DIM*DIM], s_wql[DIM*DIM];
__device__ __align__(16) __nv_bfloat16 s_wkh[DIM*DIM], s_wkl[DIM*DIM];
__device__ __align__(16) __nv_bfloat16 s_wvh[DIM*DIM], s_wvl[DIM*DIM];
__device__ __align__(16) __nv_bfloat16 s_wph[DIM*DIM], s_wpl[DIM*DIM];
__device__ __align__(16) __nv_bfloat16 s_qh [BATCH*NQ*DIM],  s_ql [BATCH*NQ*DIM];   // q split
__device__ __align__(16) __nv_bfloat16 s_kh [BATCH*NKV*DIM], s_kl [BATCH*NKV*DIM];  // compacted k split
__device__ __align__(16) __nv_bfloat16 s_vth[BATCH*DIM*NKV], s_vtl[BATCH*DIM*NKV];  // compacted vT split
__device__ __align__(16) __nv_bfloat16 s_aph[(size_t)BATCH*NQ*NKV];                 // compacted probs hi
__device__ __align__(16) __nv_bfloat16 s_apl[(size_t)BATCH*NQ*NKV];                 // compacted probs lo
__device__ __align__(16) __nv_bfloat16 s_oh [BATCH*NQ*DIM],  s_ol [BATCH*NQ*DIM];   // x split
__device__ __align__(16) float g_attn[(size_t)BATCH*NQ*NKV];                        // compacted scores
__device__ int g_idx[BATCH*NKV];
__device__ int g_cnt[BATCH];
__device__ int g_cntp[BATCH];

// ============================================================================
// helpers
// ============================================================================
__device__ __forceinline__ uint32_t smem_u32(const void* p) {
    uint32_t a;
    asm("{ .reg .u64 t; cvta.to.shared.u64 t, %1; cvt.u32.u64 %0, t; }"
        : "=r"(a) : "l"(p));
    return a;
}
__device__ __forceinline__ void cp_async16(uint32_t saddr, const void* gaddr) {
    asm volatile("cp.async.cg.shared.global [%0], [%1], 16;"
                 :: "r"(saddr), "l"(gaddr) : "memory");
}
__device__ __forceinline__ void cp_commit() {
    asm volatile("cp.async.commit_group;" ::: "memory");
}
__device__ __forceinline__ void cp_wait2() {
    asm volatile("cp.async.wait_group 2;" ::: "memory");
}
__device__ __forceinline__ void cp_wait1() {
    asm volatile("cp.async.wait_group 1;" ::: "memory");
}
__device__ __forceinline__ void cp_wait0() {
    asm volatile("cp.async.wait_group 0;" ::: "memory");
}

// mma.sync m16n8k16 bf16: d += a*b (f32 accumulators in-place)
__device__ __forceinline__ void mma_bf16(float* d, const uint32_t* a, const uint32_t* b) {
    asm volatile(
        "mma.sync.aligned.m16n8k16.row.col.f32.bf16.bf16.f32 "
        "{%0,%1,%2,%3}, {%4,%5,%6,%7}, {%8,%9}, {%0,%1,%2,%3};"
        : "+f"(d[0]), "+f"(d[1]), "+f"(d[2]), "+f"(d[3])
        : "r"(a[0]), "r"(a[1]), "r"(a[2]), "r"(a[3]), "r"(b[0]), "r"(b[1]));
}

__device__ __forceinline__ void ldsm_x4(uint32_t& r0, uint32_t& r1,
                                        uint32_t& r2, uint32_t& r3, uint32_t addr) {
    asm volatile("ldmatrix.sync.aligned.m8n8.x4.shared.b16 {%0,%1,%2,%3}, [%4];"
                 : "=r"(r0), "=r"(r1), "=r"(r2), "=r"(r3) : "r"(addr));
}

// split (x,y) -> packed bf16x2 hi (x in low 16) + packed bf16x2 lo residuals
__device__ __forceinline__ void pack_split(float x, float y, uint32_t& h, uint32_t& l) {
    asm("cvt.rn.bf16x2.f32 %0, %1, %2;" : "=r"(h) : "f"(y), "f"(x));
    float h0 = __uint_as_float(h << 16);
    float h1 = __uint_as_float(h & 0xFFFF0000u);
    asm("cvt.rn.bf16x2.f32 %0, %1, %2;" : "=r"(l) : "f"(y - h1), "f"(x - h0));
}

// ============================================================================
// mask scan: per batch, build compact index list of kept positions
// ============================================================================
__global__ void __launch_bounds__(1024) mask_scan_kernel(
    const int* __restrict__ mask, int* __restrict__ idx,
    int* __restrict__ cnt, int* __restrict__ cntp)
{
    const int b = blockIdx.x;
    const int t = threadIdx.x;
    const int* m = mask + b * NKV;
    __shared__ int sums[1024];

    int v[4], s = 0;
    #pragma unroll
    for (int i = 0; i < 4; i++) { v[i] = m[t * 4 + i] ? 1 : 0; s += v[i]; }
    sums[t] = s;
    __syncthreads();

    for (int off = 1; off < 1024; off <<= 1) {
        int x = (t >= off) ? sums[t - off] : 0;
        __syncthreads();
        sums[t] += x;
        __syncthreads();
    }

    int o = sums[t] - s;
    #pragma unroll
    for (int i = 0; i < 4; i++)
        if (v[i]) idx[b * NKV + o++] = t * 4 + i;

    if (t == 1023) {
        cnt[b]  = sums[1023];
        cntp[b] = (sums[1023] + 127) & ~127;
    }
}

// ============================================================================
// gather kept q_x rows (by idx) and split to bf16 hi/lo; zero the pad rows.
// ============================================================================
__global__ void __launch_bounds__(128) gather_split_kernel(
    const float* __restrict__ qx, const int* __restrict__ idx,
    const int* __restrict__ cnt, const int* __restrict__ cntp,
    __nv_bfloat16* __restrict__ xh, __nv_bfloat16* __restrict__ xl)
{
    const int b = blockIdx.y;
    const int j = blockIdx.x;
    if (j >= cntp[b]) return;

    const size_t drow = ((size_t)b * NKV + j) * DIM;
    uint2* dh = (uint2*)(xh + drow) + threadIdx.x;
    uint2* dl = (uint2*)(xl + drow) + threadIdx.x;

    if (j < cnt[b]) {
        const int r = idx[b * NKV + j];
        float4 vv = *((const float4*)(qx + ((size_t)b * NKV + r) * DIM) + threadIdx.x);
        uint32_t h0, l0, h1, l1;
        pack_split(vv.x, vv.y, h0, l0);
        pack_split(vv.z, vv.w, h1, l1);
        *dh = make_uint2(h0, h1);
        *dl = make_uint2(l0, l1);
    } else {
        *dh = make_uint2(0u, 0u);
        *dl = make_uint2(0u, 0u);
    }
}

// ============================================================================
// elementwise fp32 -> (hi, lo) bf16 split
// ============================================================================
__global__ void __launch_bounds__(256) split_kernel(
    const float* __restrict__ in, __nv_bfloat16* __restrict__ h,
    __nv_bfloat16* __restrict__ l, int n4)
{
    int i = blockIdx.x * 256 + threadIdx.x;
    if (i >= n4) return;
    float4 v = ((const float4*)in)[i];
    uint32_t h0, l0, h1, l1;
    pack_split(v.x, v.y, h0, l0);
    pack_split(v.z, v.w, h1, l1);
    ((uint2*)h)[i] = make_uint2(h0, h1);
    ((uint2*)l)[i] = make_uint2(l0, l1);
}

__global__ void __launch_bounds__(256) split4_kernel(
    const float* __restrict__ w0, const float* __restrict__ w1,
    const float* __restrict__ w2, const float* __restrict__ w3,
    __nv_bfloat16* __restrict__ h0o, __nv_bfloat16* __restrict__ l0o,
    __nv_bfloat16* __restrict__ h1o, __nv_bfloat16* __restrict__ l1o,
    __nv_bfloat16* __restrict__ h2o, __nv_bfloat16* __restrict__ l2o,
    __nv_bfloat16* __restrict__ h3o, __nv_bfloat16* __restrict__ l3o,
    int n4)
{
    int i = blockIdx.x * 256 + threadIdx.x;
    if (i >= n4) return;
    const float* in = blockIdx.y == 0 ? w0 : blockIdx.y == 1 ? w1
                    : blockIdx.y == 2 ? w2 : w3;
    __nv_bfloat16* h = blockIdx.y == 0 ? h0o : blockIdx.y == 1 ? h1o
                     : blockIdx.y == 2 ? h2o : h3o;
    __nv_bfloat16* l = blockIdx.y == 0 ? l0o : blockIdx.y == 1 ? l1o
                     : blockIdx.y == 2 ? l2o : l3o;
    float4 v = ((const float4*)in)[i];
    uint32_t ha, la, hb, lb;
    pack_split(v.x, v.y, ha, la);
    pack_split(v.z, v.w, hb, lb);
    ((uint2*)h)[i] = make_uint2(ha, hb);
    ((uint2*)l)[i] = make_uint2(la, lb);
}

// ============================================================================
// bf16x3 GEMM NT, 128 threads (4 warps, 2x2), warp tile 64x64, ldmatrix,
// SW128-swizzled packed rows [hi 32bf16 | lo 32bf16] = 128B, 3-stage cp.async.
//   C[M,N] = alpha * (Ah+Al)[M,K] @ (Bh+Bl)[N,K]^T   (lo*lo dropped)
// CTA tile 128x128, K-tile 32 (2 x k16). Stage = A(16KB) + B(16KB) = 32KB;
// 3 stages x 2 CTAs = 192KB smem/SM. Swizzle: 16B-chunk c -> c ^ (row & 7),
// conflict-free for both ldmatrix (8 rows x 1 chunk) and the loader mapping
// (8 consecutive rows x same chunk per quarter-warp).
// ldA/ldB row strides; mlim/nlim per-batch tile bounds; kdyn per-batch K.
// ============================================================================
#define TILE_B    (128 * 128)              // 16384 B per tile array
#define STAGE_B   (2 * TILE_B)             // A + B = 32768
#define NSTAGE    3
#define GEMM_SMEM (NSTAGE * STAGE_B)       // 98304

__global__ void __launch_bounds__(128, 2) gemm_nt_split(
    const __nv_bfloat16* __restrict__ Ah, const __nv_bfloat16* __restrict__ Al,
    const __nv_bfloat16* __restrict__ Bh, const __nv_bfloat16* __restrict__ Bl,
    float* __restrict__ Cf,
    __nv_bfloat16* __restrict__ Ch, __nv_bfloat16* __restrict__ Cl,
    int M, int N, int K, int ldA, int ldB,
    size_t sA, size_t sB, size_t sC, float alpha,
    const int* __restrict__ mlim, const int* __restrict__ nlim,
    const int* __restrict__ kdyn)
{
    extern __shared__ __align__(1024) char smem[];
    const uint32_t sbase = smem_u32(smem);

    const int m0 = blockIdx.y * 128;
    const int n0 = blockIdx.x * 128;
    if (mlim && m0 >= mlim[blockIdx.z]) return;
    if (nlim && n0 >= nlim[blockIdx.z]) return;
    if (kdyn) K = kdyn[blockIdx.z];

    const int t    = threadIdx.x;
    const int wid  = t >> 5;
    const int lane = t & 31;
    const int g    = lane >> 2;
    const int c    = lane & 3;
    const int warp_m = wid >> 1;    // 0..1
    const int warp_n = wid & 1;     // 0..1

    // ldmatrix per-lane row/chunk components
    const int a_row = lane & 15;                    // row within 16-row mt block
    const int a_ch  = lane >> 4;                    // k-half chunk 0/1
    const int b_row = (lane & 7) + ((lane >> 4) << 3);  // row within 16-row nt pair
    const int b_ch  = (lane >> 3) & 1;              // k-half chunk 0/1

    // loader per-lane mapping: row = ph*16 + (t&15), chunk = t>>4 (0..7)
    const int l_row = t & 15;
    const int l_ch  = t >> 4;                       // 0..7: 0-3 = hi, 4-7 = lo

    Ah += (size_t)blockIdx.z * sA;  Al += (size_t)blockIdx.z * sA;
    Bh += (size_t)blockIdx.z * sB;  Bl += (size_t)blockIdx.z * sB;

    const __nv_bfloat16* srcA = (l_ch < 4) ? Ah : Al;
    const __nv_bfloat16* srcB = (l_ch < 4) ? Bh : Bl;
    const int kc8 = (l_ch & 3) * 8;                 // k offset of this 16B chunk

    auto load_tile = [&](int kt, int s) {
        const uint32_t st = sbase + (uint32_t)(s * STAGE_B);
        const int kb = kt * 32;
        #pragma unroll
        for (int ph = 0; ph < 8; ph++) {
            int row = ph * 16 + l_row;
            uint32_t so = (uint32_t)(row * 128 + ((l_ch ^ (row & 7)) * 16));
            cp_async16(st + so,          srcA + (size_t)(m0 + row) * ldA + kb + kc8);
            cp_async16(st + TILE_B + so, srcB + (size_t)(n0 + row) * ldB + kb + kc8);
        }
        cp_commit();
    };

    float acc[4][8][4] = {};   // [mtile 16-rows][ntile 8-cols][reg]

    const int nkt = K >> 5;    // >= 4 always here
    load_tile(0, 0);
    load_tile(1, 1);

    for (int kt = 0; kt < nkt; kt++) {
        const int s = kt % NSTAGE;
        if (kt + 2 < nkt) load_tile(kt + 2, (kt + 2) % NSTAGE);
        const int rem = nkt - 1 - kt;
        if (rem >= 2) cp_wait2();
        else if (rem == 1) cp_wait1();
        else cp_wait0();
        __syncthreads();

        const uint32_t aT = sbase + s * STAGE_B;
        const uint32_t bT = aT + TILE_B;

        #pragma unroll
        for (int ks2 = 0; ks2 < 2; ks2++) {
            // B fragments for all 8 n-tiles via 4+4 LDSM.x4 (2 nt per LDSM)
            uint32_t bh[8][2], bl[8][2];
            #pragma unroll
            for (int p = 0; p < 4; p++) {
                int row = warp_n * 64 + p * 16 + b_row;
                int ch  = ks2 * 2 + b_ch;
                uint32_t ahi = bT + row * 128 + ((ch       ^ (row & 7)) * 16);
                uint32_t alo = bT + row * 128 + (((ch + 4) ^ (row & 7)) * 16);
                ldsm_x4(bh[2*p][0], bh[2*p][1], bh[2*p+1][0], bh[2*p+1][1], ahi);
                ldsm_x4(bl[2*p][0], bl[2*p][1], bl[2*p+1][0], bl[2*p+1][1], alo);
            }

            #pragma unroll
            for (int mt = 0; mt < 4; mt++) {
                int row = warp_m * 64 + mt * 16 + a_row;
                int ch  = ks2 * 2 + a_ch;
                uint32_t ahi = aT + row * 128 + ((ch       ^ (row & 7)) * 16);
                uint32_t alo = aT + row * 128 + (((ch + 4) ^ (row & 7)) * 16);
                uint32_t ah[4], al[4];
                ldsm_x4(ah[0], ah[1], ah[2], ah[3], ahi);
                ldsm_x4(al[0], al[1], al[2], al[3], alo);
                #pragma unroll
                for (int nt = 0; nt < 8; nt++) {
                    mma_bf16(acc[mt][nt], al, bh[nt]);   // small terms first
                    mma_bf16(acc[mt][nt], ah, bl[nt]);
                    mma_bf16(acc[mt][nt], ah, bh[nt]);
                }
            }
        }
        __syncthreads();
    }

    if (Cf) {
        Cf += (size_t)blockIdx.z * sC;
        #pragma unroll
        for (int mt = 0; mt < 4; mt++) {
            const int row = m0 + warp_m * 64 + mt * 16 + g;
            #pragma unroll
            for (int nt = 0; nt < 8; nt++) {
                const int col = n0 + warp_n * 64 + nt * 8 + 2 * c;
                *(float2*)(Cf + (size_t)row * N + col) =
                    make_float2(acc[mt][nt][0] * alpha, acc[mt][nt][1] * alpha);
                *(float2*)(Cf + (size_t)(row + 8) * N + col) =
                    make_float2(acc[mt][nt][2] * alpha, acc[mt][nt][3] * alpha);
            }
        }
    } else {
        Ch += (size_t)blockIdx.z * sC;
        Cl += (size_t)blockIdx.z * sC;
        #pragma unroll
        for (int mt = 0; mt < 4; mt++) {
            const int row = m0 + warp_m * 64 + mt * 16 + g;
            #pragma unroll
            for (int nt = 0; nt < 8; nt++) {
                const int col = n0 + warp_n * 64 + nt * 8 + 2 * c;
                uint32_t h, l;
                pack_split(acc[mt][nt][0] * alpha, acc[mt][nt][1] * alpha, h, l);
                *(uint32_t*)(Ch + (size_t)row * N + col) = h;
                *(uint32_t*)(Cl + (size_t)row * N + col) = l;
                pack_split(acc[mt][nt][2] * alpha, acc[mt][nt][3] * alpha, h, l);
                *(uint32_t*)(Ch + (size_t)(row + 8) * N + col) = h;
                *(uint32_t*)(Cl + (size_t)(row + 8) * N + col) = l;
            }
        }
    }
}

// ============================================================================
// softmax over compacted scores: row width cnt[b] (pad to cntp[b] with P=0).
// ============================================================================
__global__ void __launch_bounds__(256) softmax_c_kernel(
    const float* __restrict__ attn, const int* __restrict__ cnt,
    const int* __restrict__ cntp,
    __nv_bfloat16* __restrict__ Ph, __nv_bfloat16* __restrict__ Pl)
{
    const int row = blockIdx.x;
    const int b   = row >> 10;             // NQ = 1024
    const int cn  = cnt[b];
    const int cp  = cntp[b];
    const float2* p = (const float2*)(attn + (size_t)row * NKV);

    float2 v[8];
    float mx = -3.0e38f;
    #pragma unroll
    for (int i = 0; i < 8; i++) {
        int j2 = threadIdx.x + i * 256;
        int j  = 2 * j2;
        float2 x = make_float2(-3.0e38f, -3.0e38f);
        if (j < cp) {
            x = p[j2];
            if (j     >= cn) x.x = -3.0e38f;
            if (j + 1 >= cn) x.y = -3.0e38f;
        }
        v[i] = x;
        mx = fmaxf(mx, fmaxf(x.x, x.y));
    }

    __shared__ float red[8];
    #pragma unroll
    for (int o = 16; o; o >>= 1) mx = fmaxf(mx, __shfl_xor_sync(0xffffffffu, mx, o));
    if ((threadIdx.x & 31) == 0) red[threadIdx.x >> 5] = mx;
    __syncthreads();
    float bm = red[0];
    #pragma unroll
    for (int w = 1; w < 8; w++) bm = fmaxf(bm, red[w]);
    __syncthreads();

    float sum = 0.0f;
    #pragma unroll
    for (int i = 0; i < 8; i++) {
        v[i].x = __expf(v[i].x - bm);
        v[i].y = __expf(v[i].y - bm);
        sum += v[i].x + v[i].y;
    }
    #pragma unroll
    for (int o = 16; o; o >>= 1) sum += __shfl_xor_sync(0xffffffffu, sum, o);
    if ((threadIdx.x & 31) == 0) red[threadIdx.x >> 5] = sum;
    __syncthreads();
    float ts = red[0];
    #pragma unroll
    for (int w = 1; w < 8; w++) ts += red[w];
    float inv = 1.0f / ts;

    #pragma unroll
    for (int i = 0; i < 8; i++) {
        int j2 = threadIdx.x + i * 256;
        int j  = 2 * j2;
        if (j < cp) {
            uint32_t h, l;
            pack_split(v[i].x * inv, v[i].y * inv, h, l);
            *(uint32_t*)(Ph + (size_t)row * NKV + j) = h;
            *(uint32_t*)(Pl + (size_t)row * NKV + j) = l;
        }
    }
}

// ============================================================================
// launch
// ============================================================================
extern "C" void kernel_launch(void* const* d_in, const int* in_sizes, int n_in,
                              void* d_out, int out_size)
{
    const float* prototype = (const float*)d_in[0];
    const float* q_x       = (const float*)d_in[1];
    const int*   mask      = (const int*)  d_in[2];
    const float* Wq        = (const float*)d_in[3];
    const float* Wk        = (const float*)d_in[4];
    const float* Wv        = (const float*)d_in[5];
    const float* Wproj     = (const float*)d_in[6];
    float* out = (float*)d_out;

    __nv_bfloat16 *ph, *pl, *xh, *xl, *wqh, *wql, *wkh, *wkl, *wvh, *wvl,
                  *wph, *wpl, *qh, *ql, *kh, *kl, *vth, *vtl, *aph, *apl, *oh, *ol;
    float* attn;
    int *idx, *cnt, *cntp;
    cudaGetSymbolAddress((void**)&ph,  s_ph);  cudaGetSymbolAddress((void**)&pl,  s_pl);
    cudaGetSymbolAddress((void**)&xh,  s_xh);  cudaGetSymbolAddress((void**)&xl,  s_xl);
    cudaGetSymbolAddress((void**)&wqh, s_wqh); cudaGetSymbolAddress((void**)&wql, s_wql);
    cudaGetSymbolAddress((void**)&wkh, s_wkh); cudaGetSymbolAddress((void**)&wkl, s_wkl);
    cudaGetSymbolAddress((void**)&wvh, s_wvh); cudaGetSymbolAddress((void**)&wvl, s_wvl);
    cudaGetSymbolAddress((void**)&wph, s_wph); cudaGetSymbolAddress((void**)&wpl, s_wpl);
    cudaGetSymbolAddress((void**)&qh,  s_qh);  cudaGetSymbolAddress((void**)&ql,  s_ql);
    cudaGetSymbolAddress((void**)&kh,  s_kh);  cudaGetSymbolAddress((void**)&kl,  s_kl);
    cudaGetSymbolAddress((void**)&vth, s_vth); cudaGetSymbolAddress((void**)&vtl, s_vtl);
    cudaGetSymbolAddress((void**)&aph, s_aph); cudaGetSymbolAddress((void**)&apl, s_apl);
    cudaGetSymbolAddress((void**)&oh,  s_oh);  cudaGetSymbolAddress((void**)&ol,  s_ol);
    cudaGetSymbolAddress((void**)&attn, g_attn);
    cudaGetSymbolAddress((void**)&idx,  g_idx);
    cudaGetSymbolAddress((void**)&cnt,  g_cnt);
    cudaGetSymbolAddress((void**)&cntp, g_cntp);

    cudaFuncSetAttribute(gemm_nt_split,
                         cudaFuncAttributeMaxDynamicSharedMemorySize, GEMM_SMEM);

    const float scale = 0.04419417382415922f;  // 1/sqrt(512)
    dim3 blk(128);

    // mask scan + gather/split of kept q_x rows
    mask_scan_kernel<<<BATCH, 1024>>>(mask, idx, cnt, cntp);
    gather_split_kernel<<<dim3(NKV, BATCH), 128>>>(q_x, idx, cnt, cntp, xh, xl);

    // splits of dense inputs
    split_kernel<<<(BATCH*NQ*DIM/4 + 255)/256, 256>>>(prototype, ph, pl, BATCH*NQ*DIM/4);
    split4_kernel<<<dim3((DIM*DIM/4 + 255)/256, 4), 256>>>(
        Wq, Wk, Wv, Wproj, wqh, wql, wkh, wkl, wvh, wvl, wph, wpl, DIM*DIM/4);

    // q = prototype @ Wq^T : M=8192, N=512, K=512
    gemm_nt_split<<<dim3(DIM/128, (BATCH*NQ)/128, 1), blk, GEMM_SMEM>>>(
        ph, pl, wqh, wql, nullptr, qh, ql,
        BATCH*NQ, DIM, DIM, DIM, DIM, 0, 0, 0, 1.0f,
        nullptr, nullptr, nullptr);

    // kc[b] = xc[b] @ Wk^T : per batch M=cntp[b], N=512, K=512
    gemm_nt_split<<<dim3(DIM/128, NKV/128, BATCH), blk, GEMM_SMEM>>>(
        xh, xl, wkh, wkl, nullptr, kh, kl,
        NKV, DIM, DIM, DIM, DIM,
        (size_t)NKV*DIM, 0, (size_t)NKV*DIM, 1.0f,
        cntp, nullptr, nullptr);

    // vTc[b] = Wv @ xc[b]^T : per batch M=512, N=cntp[b], K=512
    gemm_nt_split<<<dim3(NKV/128, DIM/128, BATCH), blk, GEMM_SMEM>>>(
        wvh, wvl, xh, xl, nullptr, vth, vtl,
        DIM, NKV, DIM, DIM, DIM,
        0, (size_t)NKV*DIM, (size_t)DIM*NKV, 1.0f,
        nullptr, cntp, nullptr);

    // attn[b] = scale * q[b] @ kc[b]^T : M=1024, N=cntp[b], K=512
    gemm_nt_split<<<dim3(NKV/128, NQ/128, BATCH), blk, GEMM_SMEM>>>(
        qh, ql, kh, kl, attn, nullptr, nullptr,
        NQ, NKV, DIM, DIM, DIM,
        (size_t)NQ*DIM, (size_t)NKV*DIM, (size_t)NQ*NKV, scale,
        nullptr, cntp, nullptr);

    // softmax over compacted width -> split probs (0 in pad region)
    softmax_c_kernel<<<BATCH*NQ, 256>>>(attn, cnt, cntp, aph, apl);

    // x[b] = Pc[b] @ vTc[b]^T : M=1024, N=512, K=cntp[b]
    gemm_nt_split<<<dim3(DIM/128, NQ/128, BATCH), blk, GEMM_SMEM>>>(
        aph, apl, vth, vtl, nullptr, oh, ol,
        NQ, DIM, NKV, NKV, NKV,
        (size_t)NQ*NKV, (size_t)DIM*NKV, (size_t)NQ*DIM, 1.0f,
        nullptr, nullptr, cntp);

    // out = x @ Wproj^T : M=8192, N=512, K=512
    gemm_nt_split<<<dim3(DIM/128, (BATCH*NQ)/128, 1), blk, GEMM_SMEM>>>(
        oh, ol, wph, wpl, out, nullptr, nullptr,
        BATCH*NQ, DIM, DIM, DIM, DIM, 0, 0, 0, 1.0f,
        nullptr, nullptr, nullptr);
}

// round 12
// speedup vs baseline: 1.2113x; 1.2113x over previous
#include <cuda_runtime.h>
#include <cuda_bf16.h>
#include <cstdint>
#include <math.h>

#define BATCH 8
#define NQ    1024
#define NKV   4096
#define DIM   512

// ---------------- scratch (device globals: allocation-free) ----------------
__device__ __align__(16) __nv_bfloat16 s_ph [BATCH*NQ*DIM],  s_pl [BATCH*NQ*DIM];   // prototype split
__device__ __align__(16) __nv_bfloat16 s_xh [BATCH*NKV*DIM], s_xl [BATCH*NKV*DIM];  // compacted q_x split
__device__ __align__(16) __nv_bfloat16 s_wqth[DIM*DIM], s_wqtl[DIM*DIM];            // Wq^T split
__device__ __align__(16) __nv_bfloat16 s_wkth[DIM*DIM], s_wktl[DIM*DIM];            // Wk^T split
__device__ __align__(16) __nv_bfloat16 s_wvth[DIM*DIM], s_wvtl[DIM*DIM];            // Wv^T split
__device__ __align__(16) __nv_bfloat16 s_wph [DIM*DIM], s_wpl [DIM*DIM];            // Wproj split
__device__ __align__(16) __nv_bfloat16 s_gth [DIM*DIM], s_gtl [DIM*DIM];            // Gt = Wk^T.Wq folded
__device__ __align__(16) __nv_bfloat16 s_hth [DIM*DIM], s_htl [DIM*DIM];            // Ht = Wproj.Wv folded
__device__ __align__(16) __nv_bfloat16 s_qh [BATCH*NQ*DIM],  s_ql [BATCH*NQ*DIM];   // q' = proto.G split
__device__ __align__(16) __nv_bfloat16 s_uth[BATCH*DIM*NKV], s_utl[BATCH*DIM*NKV];  // uT = Ht.xc^T split
__device__ __align__(16) __nv_bfloat16 s_aph[(size_t)BATCH*NQ*NKV];                 // probs hi
__device__ __align__(16) __nv_bfloat16 s_apl[(size_t)BATCH*NQ*NKV];                 // probs lo
__device__ __align__(16) float g_attn[(size_t)BATCH*NQ*NKV];                        // compacted scores
__device__ int g_idx[BATCH*NKV];
__device__ int g_cnt[BATCH];
__device__ int g_cntp[BATCH];

// ============================================================================
// helpers
// ============================================================================
__device__ __forceinline__ uint32_t smem_u32(const void* p) {
    uint32_t a;
    asm("{ .reg .u64 t; cvta.to.shared.u64 t, %1; cvt.u32.u64 %0, t; }"
        : "=r"(a) : "l"(p));
    return a;
}
__device__ __forceinline__ void cp_async16(uint32_t saddr, const void* gaddr) {
    asm volatile("cp.async.ca.shared.global [%0], [%1], 16;"
                 :: "r"(saddr), "l"(gaddr) : "memory");
}
__device__ __forceinline__ void cp_commit() {
    asm volatile("cp.async.commit_group;" ::: "memory");
}
__device__ __forceinline__ void cp_wait1() {
    asm volatile("cp.async.wait_group 1;" ::: "memory");
}
__device__ __forceinline__ void cp_wait0() {
    asm volatile("cp.async.wait_group 0;" ::: "memory");
}

// mma.sync m16n8k16 bf16: d += a*b (f32 accumulators in-place)
__device__ __forceinline__ void mma_bf16(float* d, const uint32_t* a, const uint32_t* b) {
    asm volatile(
        "mma.sync.aligned.m16n8k16.row.col.f32.bf16.bf16.f32 "
        "{%0,%1,%2,%3}, {%4,%5,%6,%7}, {%8,%9}, {%0,%1,%2,%3};"
        : "+f"(d[0]), "+f"(d[1]), "+f"(d[2]), "+f"(d[3])
        : "r"(a[0]), "r"(a[1]), "r"(a[2]), "r"(a[3]), "r"(b[0]), "r"(b[1]));
}

__device__ __forceinline__ void ldsm_x4(uint32_t& r0, uint32_t& r1,
                                        uint32_t& r2, uint32_t& r3, uint32_t addr) {
    asm volatile("ldmatrix.sync.aligned.m8n8.x4.shared.b16 {%0,%1,%2,%3}, [%4];"
                 : "=r"(r0), "=r"(r1), "=r"(r2), "=r"(r3) : "r"(addr));
}

// split (x,y) -> packed bf16x2 hi (x in low 16) + packed bf16x2 lo residuals
__device__ __forceinline__ void pack_split(float x, float y, uint32_t& h, uint32_t& l) {
    asm("cvt.rn.bf16x2.f32 %0, %1, %2;" : "=r"(h) : "f"(y), "f"(x));
    float h0 = __uint_as_float(h << 16);
    float h1 = __uint_as_float(h & 0xFFFF0000u);
    asm("cvt.rn.bf16x2.f32 %0, %1, %2;" : "=r"(l) : "f"(y - h1), "f"(x - h0));
}

// ============================================================================
// mask scan: per batch, build compact index list of kept positions
// ============================================================================
__global__ void __launch_bounds__(1024) mask_scan_kernel(
    const int* __restrict__ mask, int* __restrict__ idx,
    int* __restrict__ cnt, int* __restrict__ cntp)
{
    const int b = blockIdx.x;
    const int t = threadIdx.x;
    const int* m = mask + b * NKV;
    __shared__ int sums[1024];

    int v[4], s = 0;
    #pragma unroll
    for (int i = 0; i < 4; i++) { v[i] = m[t * 4 + i] ? 1 : 0; s += v[i]; }
    sums[t] = s;
    __syncthreads();

    for (int off = 1; off < 1024; off <<= 1) {
        int x = (t >= off) ? sums[t - off] : 0;
        __syncthreads();
        sums[t] += x;
        __syncthreads();
    }

    int o = sums[t] - s;
    #pragma unroll
    for (int i = 0; i < 4; i++)
        if (v[i]) idx[b * NKV + o++] = t * 4 + i;

    if (t == 1023) {
        cnt[b]  = sums[1023];
        cntp[b] = (sums[1023] + 127) & ~127;
    }
}

// ============================================================================
// gather kept q_x rows (by idx) and split to bf16 hi/lo; zero the pad rows.
// ============================================================================
__global__ void __launch_bounds__(128) gather_split_kernel(
    const float* __restrict__ qx, const int* __restrict__ idx,
    const int* __restrict__ cnt, const int* __restrict__ cntp,
    __nv_bfloat16* __restrict__ xh, __nv_bfloat16* __restrict__ xl)
{
    const int b = blockIdx.y;
    const int j = blockIdx.x;
    if (j >= cntp[b]) return;

    const size_t drow = ((size_t)b * NKV + j) * DIM;
    uint2* dh = (uint2*)(xh + drow) + threadIdx.x;
    uint2* dl = (uint2*)(xl + drow) + threadIdx.x;

    if (j < cnt[b]) {
        const int r = idx[b * NKV + j];
        float4 vv = *((const float4*)(qx + ((size_t)b * NKV + r) * DIM) + threadIdx.x);
        uint32_t h0, l0, h1, l1;
        pack_split(vv.x, vv.y, h0, l0);
        pack_split(vv.z, vv.w, h1, l1);
        *dh = make_uint2(h0, h1);
        *dl = make_uint2(l0, l1);
    } else {
        *dh = make_uint2(0u, 0u);
        *dl = make_uint2(0u, 0u);
    }
}

// ============================================================================
// elementwise fp32 -> (hi, lo) bf16 split
// ============================================================================
__global__ void __launch_bounds__(256) split_kernel(
    const float* __restrict__ in, __nv_bfloat16* __restrict__ h,
    __nv_bfloat16* __restrict__ l, int n4)
{
    int i = blockIdx.x * 256 + threadIdx.x;
    if (i >= n4) return;
    float4 v = ((const float4*)in)[i];
    uint32_t h0, l0, h1, l1;
    pack_split(v.x, v.y, h0, l0);
    pack_split(v.z, v.w, h1, l1);
    ((uint2*)h)[i] = make_uint2(h0, h1);
    ((uint2*)l)[i] = make_uint2(l0, l1);
}

// ============================================================================
// transpose + split for 3 weight matrices: out[d,e] = in[e,d], bf16 hi/lo
// grid (16,16,3), block (32,32)
// ============================================================================
__global__ void __launch_bounds__(1024) transpose_split3_kernel(
    const float* __restrict__ w0, const float* __restrict__ w1,
    const float* __restrict__ w2,
    __nv_bfloat16* __restrict__ h0, __nv_bfloat16* __restrict__ l0,
    __nv_bfloat16* __restrict__ h1, __nv_bfloat16* __restrict__ l1,
    __nv_bfloat16* __restrict__ h2, __nv_bfloat16* __restrict__ l2)
{
    __shared__ float tile[32][33];
    const int z = blockIdx.z;
    const float* in = z == 0 ? w0 : (z == 1 ? w1 : w2);
    __nv_bfloat16* ho = z == 0 ? h0 : (z == 1 ? h1 : h2);
    __nv_bfloat16* lo = z == 0 ? l0 : (z == 1 ? l1 : l2);

    int x = blockIdx.x * 32 + threadIdx.x;
    int y = blockIdx.y * 32 + threadIdx.y;
    tile[threadIdx.y][threadIdx.x] = in[y * DIM + x];
    __syncthreads();

    int ox = blockIdx.y * 32 + threadIdx.x;   // out col (= original row)
    int oy = blockIdx.x * 32 + threadIdx.y;   // out row (= original col)
    float v = tile[threadIdx.x][threadIdx.y];
    __nv_bfloat16 hb = __float2bfloat16_rn(v);
    float r = v - __bfloat162float(hb);
    ho[oy * DIM + ox] = hb;
    lo[oy * DIM + ox] = __float2bfloat16_rn(r);
}

// ============================================================================
// bf16x3 GEMM NT (round-9 engine, best-measured): 128 threads (4 warps, 2x2),
// warp tile 64x64, ldmatrix, 2-stage cp.async, 80B padded rows.
//   C[M,N] = alpha * (Ah+Al)[M,K] @ (Bh+Bl)[N,K]^T   (lo*lo dropped)
// ldA/ldB row strides; mlim/nlim per-batch tile bounds; kdyn per-batch K.
// ============================================================================
#define PAD2      40
#define ROW_B     (PAD2 * 2)               // 80 bytes per row
#define TILE_B    (128 * ROW_B)            // 10240
#define STAGE_B   (4 * TILE_B)             // 40960
#define GEMM_SMEM (2 * STAGE_B)            // 81920

__global__ void __launch_bounds__(128, 2) gemm_nt_split(
    const __nv_bfloat16* __restrict__ Ah, const __nv_bfloat16* __restrict__ Al,
    const __nv_bfloat16* __restrict__ Bh, const __nv_bfloat16* __restrict__ Bl,
    float* __restrict__ Cf,
    __nv_bfloat16* __restrict__ Ch, __nv_bfloat16* __restrict__ Cl,
    int M, int N, int K, int ldA, int ldB,
    size_t sA, size_t sB, size_t sC, float alpha,
    const int* __restrict__ mlim, const int* __restrict__ nlim,
    const int* __restrict__ kdyn)
{
    extern __shared__ __align__(16) char smem[];
    const uint32_t sbase = smem_u32(smem);

    const int m0 = blockIdx.y * 128;
    const int n0 = blockIdx.x * 128;
    if (mlim && m0 >= mlim[blockIdx.z]) return;
    if (nlim && n0 >= nlim[blockIdx.z]) return;
    if (kdyn) K = kdyn[blockIdx.z];

    const int t    = threadIdx.x;
    const int wid  = t >> 5;
    const int lane = t & 31;
    const int g    = lane >> 2;
    const int c    = lane & 3;
    const int warp_m = wid >> 1;    // 0..1
    const int warp_n = wid & 1;     // 0..1

    const uint32_t a_row = lane & 15;
    const uint32_t a_kh  = (lane >> 4) * 16;
    const uint32_t b_row = (lane & 7) + ((lane >> 4) << 3);
    const uint32_t b_kh  = ((lane >> 3) & 1) * 16;

    Ah += (size_t)blockIdx.z * sA;  Al += (size_t)blockIdx.z * sA;
    Bh += (size_t)blockIdx.z * sB;  Bl += (size_t)blockIdx.z * sB;

    auto load_tile = [&](int kt, int s) {
        const uint32_t st = sbase + (uint32_t)(s * STAGE_B);
        const int kb = kt * 32;
        #pragma unroll
        for (int ph = 0; ph < 4; ph++) {
            int idx = ph * 128 + t;
            int row = idx >> 2;
            int c4  = idx & 3;
            uint32_t so = (uint32_t)(row * ROW_B + c4 * 16);
            const size_t ga = (size_t)(m0 + row) * ldA + kb + c4 * 8;
            const size_t gb = (size_t)(n0 + row) * ldB + kb + c4 * 8;
            cp_async16(st + 0 * TILE_B + so, Ah + ga);
            cp_async16(st + 1 * TILE_B + so, Al + ga);
            cp_async16(st + 2 * TILE_B + so, Bh + gb);
            cp_async16(st + 3 * TILE_B + so, Bl + gb);
        }
        cp_commit();
    };

    float acc[4][8][4] = {};

    const int nkt = K >> 5;
    load_tile(0, 0);

    for (int kt = 0; kt < nkt; kt++) {
        const int s = kt & 1;
        if (kt + 1 < nkt) {
            load_tile(kt + 1, s ^ 1);
            cp_wait1();
        } else {
            cp_wait0();
        }
        __syncthreads();

        const uint32_t aB = sbase + s * STAGE_B + warp_m * 64 * ROW_B;
        const uint32_t bB = sbase + s * STAGE_B + 2 * TILE_B + warp_n * 64 * ROW_B;

        #pragma unroll
        for (int ks2 = 0; ks2 < 2; ks2++) {
            const uint32_t kso = ks2 * 32;

            uint32_t bh[8][2], bl[8][2];
            #pragma unroll
            for (int p = 0; p < 4; p++) {
                uint32_t addr = bB + (p * 16 + b_row) * ROW_B + kso + b_kh;
                ldsm_x4(bh[2*p][0], bh[2*p][1], bh[2*p+1][0], bh[2*p+1][1], addr);
                ldsm_x4(bl[2*p][0], bl[2*p][1], bl[2*p+1][0], bl[2*p+1][1],
                        addr + TILE_B);
            }

            #pragma unroll
            for (int mt = 0; mt < 4; mt++) {
                uint32_t addr = aB + (mt * 16 + a_row) * ROW_B + kso + a_kh;
                uint32_t ah[4], al[4];
                ldsm_x4(ah[0], ah[1], ah[2], ah[3], addr);
                ldsm_x4(al[0], al[1], al[2], al[3], addr + TILE_B);
                #pragma unroll
                for (int nt = 0; nt < 8; nt++) {
                    mma_bf16(acc[mt][nt], al, bh[nt]);
                    mma_bf16(acc[mt][nt], ah, bl[nt]);
                    mma_bf16(acc[mt][nt], ah, bh[nt]);
                }
            }
        }
        __syncthreads();
    }

    if (Cf) {
        Cf += (size_t)blockIdx.z * sC;
        #pragma unroll
        for (int mt = 0; mt < 4; mt++) {
            const int row = m0 + warp_m * 64 + mt * 16 + g;
            #pragma unroll
            for (int nt = 0; nt < 8; nt++) {
                const int col = n0 + warp_n * 64 + nt * 8 + 2 * c;
                *(float2*)(Cf + (size_t)row * N + col) =
                    make_float2(acc[mt][nt][0] * alpha, acc[mt][nt][1] * alpha);
                *(float2*)(Cf + (size_t)(row + 8) * N + col) =
                    make_float2(acc[mt][nt][2] * alpha, acc[mt][nt][3] * alpha);
            }
        }
    } else {
        Ch += (size_t)blockIdx.z * sC;
        Cl += (size_t)blockIdx.z * sC;
        #pragma unroll
        for (int mt = 0; mt < 4; mt++) {
            const int row = m0 + warp_m * 64 + mt * 16 + g;
            #pragma unroll
            for (int nt = 0; nt < 8; nt++) {
                const int col = n0 + warp_n * 64 + nt * 8 + 2 * c;
                uint32_t h, l;
                pack_split(acc[mt][nt][0] * alpha, acc[mt][nt][1] * alpha, h, l);
                *(uint32_t*)(Ch + (size_t)row * N + col) = h;
                *(uint32_t*)(Cl + (size_t)row * N + col) = l;
                pack_split(acc[mt][nt][2] * alpha, acc[mt][nt][3] * alpha, h, l);
                *(uint32_t*)(Ch + (size_t)(row + 8) * N + col) = h;
                *(uint32_t*)(Cl + (size_t)(row + 8) * N + col) = l;
            }
        }
    }
}

// ============================================================================
// softmax over compacted scores: row width cnt[b] (pad to cntp[b] with P=0).
// ============================================================================
__global__ void __launch_bounds__(256) softmax_c_kernel(
    const float* __restrict__ attn, const int* __restrict__ cnt,
    const int* __restrict__ cntp,
    __nv_bfloat16* __restrict__ Ph, __nv_bfloat16* __restrict__ Pl)
{
    const int row = blockIdx.x;
    const int b   = row >> 10;             // NQ = 1024
    const int cn  = cnt[b];
    const int cp  = cntp[b];
    const float2* p = (const float2*)(attn + (size_t)row * NKV);

    float2 v[8];
    float mx = -3.0e38f;
    #pragma unroll
    for (int i = 0; i < 8; i++) {
        int j2 = threadIdx.x + i * 256;
        int j  = 2 * j2;
        float2 x = make_float2(-3.0e38f, -3.0e38f);
        if (j < cp) {
            x = p[j2];
            if (j     >= cn) x.x = -3.0e38f;
            if (j + 1 >= cn) x.y = -3.0e38f;
        }
        v[i] = x;
        mx = fmaxf(mx, fmaxf(x.x, x.y));
    }

    __shared__ float red[8];
    #pragma unroll
    for (int o = 16; o; o >>= 1) mx = fmaxf(mx, __shfl_xor_sync(0xffffffffu, mx, o));
    if ((threadIdx.x & 31) == 0) red[threadIdx.x >> 5] = mx;
    __syncthreads();
    float bm = red[0];
    #pragma unroll
    for (int w = 1; w < 8; w++) bm = fmaxf(bm, red[w]);
    __syncthreads();

    float sum = 0.0f;
    #pragma unroll
    for (int i = 0; i < 8; i++) {
        v[i].x = __expf(v[i].x - bm);
        v[i].y = __expf(v[i].y - bm);
        sum += v[i].x + v[i].y;
    }
    #pragma unroll
    for (int o = 16; o; o >>= 1) sum += __shfl_xor_sync(0xffffffffu, sum, o);
    if ((threadIdx.x & 31) == 0) red[threadIdx.x >> 5] = sum;
    __syncthreads();
    float ts = red[0];
    #pragma unroll
    for (int w = 1; w < 8; w++) ts += red[w];
    float inv = 1.0f / ts;

    #pragma unroll
    for (int i = 0; i < 8; i++) {
        int j2 = threadIdx.x + i * 256;
        int j  = 2 * j2;
        if (j < cp) {
            uint32_t h, l;
            pack_split(v[i].x * inv, v[i].y * inv, h, l);
            *(uint32_t*)(Ph + (size_t)row * NKV + j) = h;
            *(uint32_t*)(Pl + (size_t)row * NKV + j) = l;
        }
    }
}

// ============================================================================
// launch
// ============================================================================
extern "C" void kernel_launch(void* const* d_in, const int* in_sizes, int n_in,
                              void* d_out, int out_size)
{
    const float* prototype = (const float*)d_in[0];
    const float* q_x       = (const float*)d_in[1];
    const int*   mask      = (const int*)  d_in[2];
    const float* Wq        = (const float*)d_in[3];
    const float* Wk        = (const float*)d_in[4];
    const float* Wv        = (const float*)d_in[5];
    const float* Wproj     = (const float*)d_in[6];
    float* out = (float*)d_out;

    __nv_bfloat16 *ph, *pl, *xh, *xl, *wqth, *wqtl, *wkth, *wktl, *wvth, *wvtl,
                  *wph, *wpl, *gth, *gtl, *hth, *htl, *qh, *ql, *uth, *utl,
                  *aph, *apl;
    float* attn;
    int *idx, *cnt, *cntp;
    cudaGetSymbolAddress((void**)&ph,   s_ph);   cudaGetSymbolAddress((void**)&pl,   s_pl);
    cudaGetSymbolAddress((void**)&xh,   s_xh);   cudaGetSymbolAddress((void**)&xl,   s_xl);
    cudaGetSymbolAddress((void**)&wqth, s_wqth); cudaGetSymbolAddress((void**)&wqtl, s_wqtl);
    cudaGetSymbolAddress((void**)&wkth, s_wkth); cudaGetSymbolAddress((void**)&wktl, s_wktl);
    cudaGetSymbolAddress((void**)&wvth, s_wvth); cudaGetSymbolAddress((void**)&wvtl, s_wvtl);
    cudaGetSymbolAddress((void**)&wph,  s_wph);  cudaGetSymbolAddress((void**)&wpl,  s_wpl);
    cudaGetSymbolAddress((void**)&gth,  s_gth);  cudaGetSymbolAddress((void**)&gtl,  s_gtl);
    cudaGetSymbolAddress((void**)&hth,  s_hth);  cudaGetSymbolAddress((void**)&htl,  s_htl);
    cudaGetSymbolAddress((void**)&qh,   s_qh);   cudaGetSymbolAddress((void**)&ql,   s_ql);
    cudaGetSymbolAddress((void**)&uth,  s_uth);  cudaGetSymbolAddress((void**)&utl,  s_utl);
    cudaGetSymbolAddress((void**)&aph,  s_aph);  cudaGetSymbolAddress((void**)&apl,  s_apl);
    cudaGetSymbolAddress((void**)&attn, g_attn);
    cudaGetSymbolAddress((void**)&idx,  g_idx);
    cudaGetSymbolAddress((void**)&cnt,  g_cnt);
    cudaGetSymbolAddress((void**)&cntp, g_cntp);

    cudaFuncSetAttribute(gemm_nt_split,
                         cudaFuncAttributeMaxDynamicSharedMemorySize, GEMM_SMEM);

    const float scale = 0.04419417382415922f;  // 1/sqrt(512)
    dim3 blk(128);

    // mask scan + gather/split of kept q_x rows
    mask_scan_kernel<<<BATCH, 1024>>>(mask, idx, cnt, cntp);
    gather_split_kernel<<<dim3(NKV, BATCH), 128>>>(q_x, idx, cnt, cntp, xh, xl);

    // splits: prototype, Wproj (plain); Wq, Wk, Wv (transposed)
    split_kernel<<<(BATCH*NQ*DIM/4 + 255)/256, 256>>>(prototype, ph, pl, BATCH*NQ*DIM/4);
    split_kernel<<<(DIM*DIM/4 + 255)/256, 256>>>(Wproj, wph, wpl, DIM*DIM/4);
    transpose_split3_kernel<<<dim3(16, 16, 3), dim3(32, 32)>>>(
        Wq, Wk, Wv, wqth, wqtl, wkth, wktl, wvth, wvtl);

    // Gt[d',d] = sum_e Wk[e,d'] Wq[e,d]  : NT(WkT, WqT), 512x512x512 -> split
    gemm_nt_split<<<dim3(DIM/128, DIM/128, 1), blk, GEMM_SMEM>>>(
        wkth, wktl, wqth, wqtl, nullptr, gth, gtl,
        DIM, DIM, DIM, DIM, DIM, 0, 0, 0, 1.0f,
        nullptr, nullptr, nullptr);

    // Ht[g,d] = sum_f Wproj[g,f] Wv[f,d] : NT(Wproj, WvT), 512x512x512 -> split
    gemm_nt_split<<<dim3(DIM/128, DIM/128, 1), blk, GEMM_SMEM>>>(
        wph, wpl, wvth, wvtl, nullptr, hth, htl,
        DIM, DIM, DIM, DIM, DIM, 0, 0, 0, 1.0f,
        nullptr, nullptr, nullptr);

    // q'[n,d'] = sum_d proto[n,d] Gt[d',d] : NT(proto, Gt), M=8192 -> split
    gemm_nt_split<<<dim3(DIM/128, (BATCH*NQ)/128, 1), blk, GEMM_SMEM>>>(
        ph, pl, gth, gtl, nullptr, qh, ql,
        BATCH*NQ, DIM, DIM, DIM, DIM, 0, 0, 0, 1.0f,
        nullptr, nullptr, nullptr);

    // attn[b] = scale * q'[b] @ xc[b]^T : M=1024, N=cntp[b], K=512 -> fp32
    gemm_nt_split<<<dim3(NKV/128, NQ/128, BATCH), blk, GEMM_SMEM>>>(
        qh, ql, xh, xl, attn, nullptr, nullptr,
        NQ, NKV, DIM, DIM, DIM,
        (size_t)NQ*DIM, (size_t)NKV*DIM, (size_t)NQ*NKV, scale,
        nullptr, cntp, nullptr);

    // softmax over compacted width -> split probs (0 in pad region)
    softmax_c_kernel<<<BATCH*NQ, 256>>>(attn, cnt, cntp, aph, apl);

    // uT[b][g,m] = sum_d Ht[g,d] xc[b][m,d] : M=512, N=cntp[b], K=512 -> split
    gemm_nt_split<<<dim3(NKV/128, DIM/128, BATCH), blk, GEMM_SMEM>>>(
        hth, htl, xh, xl, nullptr, uth, utl,
        DIM, NKV, DIM, DIM, DIM,
        0, (size_t)NKV*DIM, (size_t)DIM*NKV, 1.0f,
        nullptr, cntp, nullptr);

    // out[b][n,g] = sum_m P[b][n,m] uT[b][g,m] : M=1024, N=512, K=cntp[b] -> fp32
    gemm_nt_split<<<dim3(DIM/128, NQ/128, BATCH), blk, GEMM_SMEM>>>(
        aph, apl, uth, utl, out, nullptr, nullptr,
        NQ, DIM, NKV, NKV, NKV,
        (size_t)NQ*NKV, (size_t)DIM*NKV, (size_t)NQ*DIM, 1.0f,
        nullptr, nullptr, cntp);
}

// round 13
// speedup vs baseline: 1.4841x; 1.2252x over previous
#include <cuda_runtime.h>
#include <cuda_fp16.h>
#include <cstdint>
#include <math.h>

#define BATCH 8
#define NQ    1024
#define NKV   4096
#define DIM   512

// ---------------- scratch (device globals: allocation-free) ----------------
__device__ __align__(16) __half s_ph [BATCH*NQ*DIM],  s_pl [BATCH*NQ*DIM];   // prototype split
__device__ __align__(16) __half s_xh [BATCH*NKV*DIM], s_xl [BATCH*NKV*DIM];  // compacted q_x split
__device__ __align__(16) __half s_wqth[DIM*DIM], s_wqtl[DIM*DIM];            // Wq^T split
__device__ __align__(16) __half s_wkth[DIM*DIM], s_wktl[DIM*DIM];            // Wk^T split
__device__ __align__(16) __half s_wvth[DIM*DIM], s_wvtl[DIM*DIM];            // Wv^T split
__device__ __align__(16) __half s_wph [DIM*DIM], s_wpl [DIM*DIM];            // Wproj split
__device__ __align__(16) __half s_gth [DIM*DIM];                             // Gt single
__device__ __align__(16) __half s_hth [DIM*DIM], s_htl [DIM*DIM];            // Ht split
__device__ __align__(16) __half s_qh [BATCH*NQ*DIM];                         // q' single
__device__ __align__(16) __half s_uth[BATCH*DIM*NKV], s_utl[BATCH*DIM*NKV];  // uT split
__device__ __align__(16) __half s_aph[(size_t)BATCH*NQ*NKV];                 // probs single
__device__ __align__(16) float g_attn[(size_t)BATCH*NQ*NKV];                 // scores fp32
__device__ int g_idx[BATCH*NKV];
__device__ int g_cnt[BATCH];
__device__ int g_cntp[BATCH];

// ============================================================================
// helpers
// ============================================================================
__device__ __forceinline__ uint32_t smem_u32(const void* p) {
    uint32_t a;
    asm("{ .reg .u64 t; cvta.to.shared.u64 t, %1; cvt.u32.u64 %0, t; }"
        : "=r"(a) : "l"(p));
    return a;
}
__device__ __forceinline__ void cp_async16(uint32_t saddr, const void* gaddr) {
    asm volatile("cp.async.ca.shared.global [%0], [%1], 16;"
                 :: "r"(saddr), "l"(gaddr) : "memory");
}
__device__ __forceinline__ void cp_commit() {
    asm volatile("cp.async.commit_group;" ::: "memory");
}
__device__ __forceinline__ void cp_wait1() {
    asm volatile("cp.async.wait_group 1;" ::: "memory");
}
__device__ __forceinline__ void cp_wait0() {
    asm volatile("cp.async.wait_group 0;" ::: "memory");
}

// mma.sync m16n8k16 fp16: d += a*b (f32 accumulators in-place)
__device__ __forceinline__ void mma_f16(float* d, const uint32_t* a, const uint32_t* b) {
    asm volatile(
        "mma.sync.aligned.m16n8k16.row.col.f32.f16.f16.f32 "
        "{%0,%1,%2,%3}, {%4,%5,%6,%7}, {%8,%9}, {%0,%1,%2,%3};"
        : "+f"(d[0]), "+f"(d[1]), "+f"(d[2]), "+f"(d[3])
        : "r"(a[0]), "r"(a[1]), "r"(a[2]), "r"(a[3]), "r"(b[0]), "r"(b[1]));
}

__device__ __forceinline__ void ldsm_x4(uint32_t& r0, uint32_t& r1,
                                        uint32_t& r2, uint32_t& r3, uint32_t addr) {
    asm volatile("ldmatrix.sync.aligned.m8n8.x4.shared.b16 {%0,%1,%2,%3}, [%4];"
                 : "=r"(r0), "=r"(r1), "=r"(r2), "=r"(r3) : "r"(addr));
}

// split (x,y) -> packed f16x2 hi (x in low 16) + packed f16x2 lo residuals
__device__ __forceinline__ void pack_split(float x, float y, uint32_t& h, uint32_t& l) {
    __half2 hh = __float22half2_rn(make_float2(x, y));
    float2 hf = __half22float2(hh);
    __half2 ll = __float22half2_rn(make_float2(x - hf.x, y - hf.y));
    h = *reinterpret_cast<uint32_t*>(&hh);
    l = *reinterpret_cast<uint32_t*>(&ll);
}
__device__ __forceinline__ uint32_t pack_h(float x, float y) {
    __half2 hh = __float22half2_rn(make_float2(x, y));
    return *reinterpret_cast<uint32_t*>(&hh);
}

// ============================================================================
// mask scan: per batch, build compact index list of kept positions
// ============================================================================
__global__ void __launch_bounds__(1024) mask_scan_kernel(
    const int* __restrict__ mask, int* __restrict__ idx,
    int* __restrict__ cnt, int* __restrict__ cntp)
{
    const int b = blockIdx.x;
    const int t = threadIdx.x;
    const int* m = mask + b * NKV;
    __shared__ int sums[1024];

    int v[4], s = 0;
    #pragma unroll
    for (int i = 0; i < 4; i++) { v[i] = m[t * 4 + i] ? 1 : 0; s += v[i]; }
    sums[t] = s;
    __syncthreads();

    for (int off = 1; off < 1024; off <<= 1) {
        int x = (t >= off) ? sums[t - off] : 0;
        __syncthreads();
        sums[t] += x;
        __syncthreads();
    }

    int o = sums[t] - s;
    #pragma unroll
    for (int i = 0; i < 4; i++)
        if (v[i]) idx[b * NKV + o++] = t * 4 + i;

    if (t == 1023) {
        cnt[b]  = sums[1023];
        cntp[b] = (sums[1023] + 127) & ~127;
    }
}

// ============================================================================
// gather kept q_x rows (by idx) and split to fp16 hi/lo; zero the pad rows.
// ============================================================================
__global__ void __launch_bounds__(128) gather_split_kernel(
    const float* __restrict__ qx, const int* __restrict__ idx,
    const int* __restrict__ cnt, const int* __restrict__ cntp,
    __half* __restrict__ xh, __half* __restrict__ xl)
{
    const int b = blockIdx.y;
    const int j = blockIdx.x;
    if (j >= cntp[b]) return;

    const size_t drow = ((size_t)b * NKV + j) * DIM;
    uint2* dh = (uint2*)(xh + drow) + threadIdx.x;
    uint2* dl = (uint2*)(xl + drow) + threadIdx.x;

    if (j < cnt[b]) {
        const int r = idx[b * NKV + j];
        float4 vv = *((const float4*)(qx + ((size_t)b * NKV + r) * DIM) + threadIdx.x);
        uint32_t h0, l0, h1, l1;
        pack_split(vv.x, vv.y, h0, l0);
        pack_split(vv.z, vv.w, h1, l1);
        *dh = make_uint2(h0, h1);
        *dl = make_uint2(l0, l1);
    } else {
        *dh = make_uint2(0u, 0u);
        *dl = make_uint2(0u, 0u);
    }
}

// ============================================================================
// elementwise fp32 -> (hi, lo) fp16 split
// ============================================================================
__global__ void __launch_bounds__(256) split_kernel(
    const float* __restrict__ in, __half* __restrict__ h,
    __half* __restrict__ l, int n4)
{
    int i = blockIdx.x * 256 + threadIdx.x;
    if (i >= n4) return;
    float4 v = ((const float4*)in)[i];
    uint32_t h0, l0, h1, l1;
    pack_split(v.x, v.y, h0, l0);
    pack_split(v.z, v.w, h1, l1);
    ((uint2*)h)[i] = make_uint2(h0, h1);
    ((uint2*)l)[i] = make_uint2(l0, l1);
}

// ============================================================================
// transpose + split for 3 weight matrices: out[d,e] = in[e,d], fp16 hi/lo
// ============================================================================
__global__ void __launch_bounds__(1024) transpose_split3_kernel(
    const float* __restrict__ w0, const float* __restrict__ w1,
    const float* __restrict__ w2,
    __half* __restrict__ h0, __half* __restrict__ l0,
    __half* __restrict__ h1, __half* __restrict__ l1,
    __half* __restrict__ h2, __half* __restrict__ l2)
{
    __shared__ float tile[32][33];
    const int z = blockIdx.z;
    const float* in = z == 0 ? w0 : (z == 1 ? w1 : w2);
    __half* ho = z == 0 ? h0 : (z == 1 ? h1 : h2);
    __half* lo = z == 0 ? l0 : (z == 1 ? l1 : l2);

    int x = blockIdx.x * 32 + threadIdx.x;
    int y = blockIdx.y * 32 + threadIdx.y;
    tile[threadIdx.y][threadIdx.x] = in[y * DIM + x];
    __syncthreads();

    int ox = blockIdx.y * 32 + threadIdx.x;
    int oy = blockIdx.x * 32 + threadIdx.y;
    float v = tile[threadIdx.x][threadIdx.y];
    __half hb = __float2half_rn(v);
    float r = v - __half2float(hb);
    ho[oy * DIM + ox] = hb;
    lo[oy * DIM + ox] = __float2half_rn(r);
}

// ============================================================================
// fp16 split GEMM NT (round-9 engine), templated on operand splits:
//   C = alpha * (Ah [+Al]) @ (Bh [+Bl])^T
// MMAs per tile: ah*bh always; +al*bh if AS; +ah*bl if BS.
// 128 threads (4 warps, 2x2), warp tile 64x64, ldmatrix, 2-stage cp.async,
// 80B padded rows. Output: fp32 (Cf) | fp16 split (Ch,Cl) | fp16 single (Ch).
// ldA/ldB row strides; mlim/nlim per-batch tile bounds; kdyn per-batch K.
// ============================================================================
#define PAD2      40
#define ROW_B     (PAD2 * 2)               // 80 bytes per row
#define TILE_B    (128 * ROW_B)            // 10240
#define STAGE_B   (4 * TILE_B)             // 40960
#define GEMM_SMEM (2 * STAGE_B)            // 81920

template<bool AS, bool BS>
__global__ void __launch_bounds__(128, 2) gemm_h(
    const __half* __restrict__ Ah, const __half* __restrict__ Al,
    const __half* __restrict__ Bh, const __half* __restrict__ Bl,
    float* __restrict__ Cf,
    __half* __restrict__ Ch, __half* __restrict__ Cl,
    int M, int N, int K, int ldA, int ldB,
    size_t sA, size_t sB, size_t sC, float alpha,
    const int* __restrict__ mlim, const int* __restrict__ nlim,
    const int* __restrict__ kdyn)
{
    extern __shared__ __align__(16) char smem[];
    const uint32_t sbase = smem_u32(smem);

    const int m0 = blockIdx.y * 128;
    const int n0 = blockIdx.x * 128;
    if (mlim && m0 >= mlim[blockIdx.z]) return;
    if (nlim && n0 >= nlim[blockIdx.z]) return;
    if (kdyn) K = kdyn[blockIdx.z];

    const int t    = threadIdx.x;
    const int wid  = t >> 5;
    const int lane = t & 31;
    const int g    = lane >> 2;
    const int c    = lane & 3;
    const int warp_m = wid >> 1;    // 0..1
    const int warp_n = wid & 1;     // 0..1

    const uint32_t a_row = lane & 15;
    const uint32_t a_kh  = (lane >> 4) * 16;
    const uint32_t b_row = (lane & 7) + ((lane >> 4) << 3);
    const uint32_t b_kh  = ((lane >> 3) & 1) * 16;

    Ah += (size_t)blockIdx.z * sA;
    Bh += (size_t)blockIdx.z * sB;
    if (AS) Al += (size_t)blockIdx.z * sA;
    if (BS) Bl += (size_t)blockIdx.z * sB;

    auto load_tile = [&](int kt, int s) {
        const uint32_t st = sbase + (uint32_t)(s * STAGE_B);
        const int kb = kt * 32;
        #pragma unroll
        for (int ph = 0; ph < 4; ph++) {
            int idx = ph * 128 + t;
            int row = idx >> 2;
            int c4  = idx & 3;
            uint32_t so = (uint32_t)(row * ROW_B + c4 * 16);
            const size_t ga = (size_t)(m0 + row) * ldA + kb + c4 * 8;
            const size_t gb = (size_t)(n0 + row) * ldB + kb + c4 * 8;
            cp_async16(st + 0 * TILE_B + so, Ah + ga);
            if (AS) cp_async16(st + 1 * TILE_B + so, Al + ga);
            cp_async16(st + 2 * TILE_B + so, Bh + gb);
            if (BS) cp_async16(st + 3 * TILE_B + so, Bl + gb);
        }
        cp_commit();
    };

    float acc[4][8][4] = {};

    const int nkt = K >> 5;
    load_tile(0, 0);

    for (int kt = 0; kt < nkt; kt++) {
        const int s = kt & 1;
        if (kt + 1 < nkt) {
            load_tile(kt + 1, s ^ 1);
            cp_wait1();
        } else {
            cp_wait0();
        }
        __syncthreads();

        const uint32_t aB = sbase + s * STAGE_B + warp_m * 64 * ROW_B;
        const uint32_t bB = sbase + s * STAGE_B + 2 * TILE_B + warp_n * 64 * ROW_B;

        #pragma unroll
        for (int ks2 = 0; ks2 < 2; ks2++) {
            const uint32_t kso = ks2 * 32;

            uint32_t bh[8][2], bl[8][2];
            #pragma unroll
            for (int p = 0; p < 4; p++) {
                uint32_t addr = bB + (p * 16 + b_row) * ROW_B + kso + b_kh;
                ldsm_x4(bh[2*p][0], bh[2*p][1], bh[2*p+1][0], bh[2*p+1][1], addr);
                if (BS)
                    ldsm_x4(bl[2*p][0], bl[2*p][1], bl[2*p+1][0], bl[2*p+1][1],
                            addr + TILE_B);
            }

            #pragma unroll
            for (int mt = 0; mt < 4; mt++) {
                uint32_t addr = aB + (mt * 16 + a_row) * ROW_B + kso + a_kh;
                uint32_t ah[4], al[4];
                ldsm_x4(ah[0], ah[1], ah[2], ah[3], addr);
                if (AS)
                    ldsm_x4(al[0], al[1], al[2], al[3], addr + TILE_B);
                #pragma unroll
                for (int nt = 0; nt < 8; nt++) {
                    if (AS) mma_f16(acc[mt][nt], al, bh[nt]);   // small terms first
                    if (BS) mma_f16(acc[mt][nt], ah, bl[nt]);
                    mma_f16(acc[mt][nt], ah, bh[nt]);
                }
            }
        }
        __syncthreads();
    }

    if (Cf) {
        Cf += (size_t)blockIdx.z * sC;
        #pragma unroll
        for (int mt = 0; mt < 4; mt++) {
            const int row = m0 + warp_m * 64 + mt * 16 + g;
            #pragma unroll
            for (int nt = 0; nt < 8; nt++) {
                const int col = n0 + warp_n * 64 + nt * 8 + 2 * c;
                *(float2*)(Cf + (size_t)row * N + col) =
                    make_float2(acc[mt][nt][0] * alpha, acc[mt][nt][1] * alpha);
                *(float2*)(Cf + (size_t)(row + 8) * N + col) =
                    make_float2(acc[mt][nt][2] * alpha, acc[mt][nt][3] * alpha);
            }
        }
    } else if (Cl) {
        Ch += (size_t)blockIdx.z * sC;
        Cl += (size_t)blockIdx.z * sC;
        #pragma unroll
        for (int mt = 0; mt < 4; mt++) {
            const int row = m0 + warp_m * 64 + mt * 16 + g;
            #pragma unroll
            for (int nt = 0; nt < 8; nt++) {
                const int col = n0 + warp_n * 64 + nt * 8 + 2 * c;
                uint32_t h, l;
                pack_split(acc[mt][nt][0] * alpha, acc[mt][nt][1] * alpha, h, l);
                *(uint32_t*)(Ch + (size_t)row * N + col) = h;
                *(uint32_t*)(Cl + (size_t)row * N + col) = l;
                pack_split(acc[mt][nt][2] * alpha, acc[mt][nt][3] * alpha, h, l);
                *(uint32_t*)(Ch + (size_t)(row + 8) * N + col) = h;
                *(uint32_t*)(Cl + (size_t)(row + 8) * N + col) = l;
            }
        }
    } else {
        Ch += (size_t)blockIdx.z * sC;
        #pragma unroll
        for (int mt = 0; mt < 4; mt++) {
            const int row = m0 + warp_m * 64 + mt * 16 + g;
            #pragma unroll
            for (int nt = 0; nt < 8; nt++) {
                const int col = n0 + warp_n * 64 + nt * 8 + 2 * c;
                *(uint32_t*)(Ch + (size_t)row * N + col) =
                    pack_h(acc[mt][nt][0] * alpha, acc[mt][nt][1] * alpha);
                *(uint32_t*)(Ch + (size_t)(row + 8) * N + col) =
                    pack_h(acc[mt][nt][2] * alpha, acc[mt][nt][3] * alpha);
            }
        }
    }
}

// ============================================================================
// softmax over compacted scores -> single fp16 probs (pad region = 0).
// ============================================================================
__global__ void __launch_bounds__(256) softmax_c_kernel(
    const float* __restrict__ attn, const int* __restrict__ cnt,
    const int* __restrict__ cntp, __half* __restrict__ Ph)
{
    const int row = blockIdx.x;
    const int b   = row >> 10;             // NQ = 1024
    const int cn  = cnt[b];
    const int cp  = cntp[b];
    const float2* p = (const float2*)(attn + (size_t)row * NKV);

    float2 v[8];
    float mx = -3.0e38f;
    #pragma unroll
    for (int i = 0; i < 8; i++) {
        int j2 = threadIdx.x + i * 256;
        int j  = 2 * j2;
        float2 x = make_float2(-3.0e38f, -3.0e38f);
        if (j < cp) {
            x = p[j2];
            if (j     >= cn) x.x = -3.0e38f;
            if (j + 1 >= cn) x.y = -3.0e38f;
        }
        v[i] = x;
        mx = fmaxf(mx, fmaxf(x.x, x.y));
    }

    __shared__ float red[8];
    #pragma unroll
    for (int o = 16; o; o >>= 1) mx = fmaxf(mx, __shfl_xor_sync(0xffffffffu, mx, o));
    if ((threadIdx.x & 31) == 0) red[threadIdx.x >> 5] = mx;
    __syncthreads();
    float bm = red[0];
    #pragma unroll
    for (int w = 1; w < 8; w++) bm = fmaxf(bm, red[w]);
    __syncthreads();

    float sum = 0.0f;
    #pragma unroll
    for (int i = 0; i < 8; i++) {
        v[i].x = __expf(v[i].x - bm);
        v[i].y = __expf(v[i].y - bm);
        sum += v[i].x + v[i].y;
    }
    #pragma unroll
    for (int o = 16; o; o >>= 1) sum += __shfl_xor_sync(0xffffffffu, sum, o);
    if ((threadIdx.x & 31) == 0) red[threadIdx.x >> 5] = sum;
    __syncthreads();
    float ts = red[0];
    #pragma unroll
    for (int w = 1; w < 8; w++) ts += red[w];
    float inv = 1.0f / ts;

    #pragma unroll
    for (int i = 0; i < 8; i++) {
        int j2 = threadIdx.x + i * 256;
        int j  = 2 * j2;
        if (j < cp)
            *(uint32_t*)(Ph + (size_t)row * NKV + j) =
                pack_h(v[i].x * inv, v[i].y * inv);
    }
}

// ============================================================================
// launch
// ============================================================================
extern "C" void kernel_launch(void* const* d_in, const int* in_sizes, int n_in,
                              void* d_out, int out_size)
{
    const float* prototype = (const float*)d_in[0];
    const float* q_x       = (const float*)d_in[1];
    const int*   mask      = (const int*)  d_in[2];
    const float* Wq        = (const float*)d_in[3];
    const float* Wk        = (const float*)d_in[4];
    const float* Wv        = (const float*)d_in[5];
    const float* Wproj     = (const float*)d_in[6];
    float* out = (float*)d_out;

    __half *ph, *pl, *xh, *xl, *wqth, *wqtl, *wkth, *wktl, *wvth, *wvtl,
           *wph, *wpl, *gth, *hth, *htl, *qh, *uth, *utl, *aph;
    float* attn;
    int *idx, *cnt, *cntp;
    cudaGetSymbolAddress((void**)&ph,   s_ph);   cudaGetSymbolAddress((void**)&pl,   s_pl);
    cudaGetSymbolAddress((void**)&xh,   s_xh);   cudaGetSymbolAddress((void**)&xl,   s_xl);
    cudaGetSymbolAddress((void**)&wqth, s_wqth); cudaGetSymbolAddress((void**)&wqtl, s_wqtl);
    cudaGetSymbolAddress((void**)&wkth, s_wkth); cudaGetSymbolAddress((void**)&wktl, s_wktl);
    cudaGetSymbolAddress((void**)&wvth, s_wvth); cudaGetSymbolAddress((void**)&wvtl, s_wvtl);
    cudaGetSymbolAddress((void**)&wph,  s_wph);  cudaGetSymbolAddress((void**)&wpl,  s_wpl);
    cudaGetSymbolAddress((void**)&gth,  s_gth);
    cudaGetSymbolAddress((void**)&hth,  s_hth);  cudaGetSymbolAddress((void**)&htl,  s_htl);
    cudaGetSymbolAddress((void**)&qh,   s_qh);
    cudaGetSymbolAddress((void**)&uth,  s_uth);  cudaGetSymbolAddress((void**)&utl,  s_utl);
    cudaGetSymbolAddress((void**)&aph,  s_aph);
    cudaGetSymbolAddress((void**)&attn, g_attn);
    cudaGetSymbolAddress((void**)&idx,  g_idx);
    cudaGetSymbolAddress((void**)&cnt,  g_cnt);
    cudaGetSymbolAddress((void**)&cntp, g_cntp);

    cudaFuncSetAttribute(gemm_h<true,true>,
                         cudaFuncAttributeMaxDynamicSharedMemorySize, GEMM_SMEM);
    cudaFuncSetAttribute(gemm_h<true,false>,
                         cudaFuncAttributeMaxDynamicSharedMemorySize, GEMM_SMEM);
    cudaFuncSetAttribute(gemm_h<false,true>,
                         cudaFuncAttributeMaxDynamicSharedMemorySize, GEMM_SMEM);

    const float scale = 0.04419417382415922f;  // 1/sqrt(512)
    dim3 blk(128);

    // mask scan + gather/split of kept q_x rows
    mask_scan_kernel<<<BATCH, 1024>>>(mask, idx, cnt, cntp);
    gather_split_kernel<<<dim3(NKV, BATCH), 128>>>(q_x, idx, cnt, cntp, xh, xl);

    // splits: prototype, Wproj (plain); Wq, Wk, Wv (transposed)
    split_kernel<<<(BATCH*NQ*DIM/4 + 255)/256, 256>>>(prototype, ph, pl, BATCH*NQ*DIM/4);
    split_kernel<<<(DIM*DIM/4 + 255)/256, 256>>>(Wproj, wph, wpl, DIM*DIM/4);
    transpose_split3_kernel<<<dim3(16, 16, 3), dim3(32, 32)>>>(
        Wq, Wk, Wv, wqth, wqtl, wkth, wktl, wvth, wvtl);

    // Gt[d',d] = sum_e Wk[e,d'] Wq[e,d] : 3-MMA fold -> single fp16
    gemm_h<true,true><<<dim3(DIM/128, DIM/128, 1), blk, GEMM_SMEM>>>(
        wkth, wktl, wqth, wqtl, nullptr, gth, nullptr,
        DIM, DIM, DIM, DIM, DIM, 0, 0, 0, 1.0f,
        nullptr, nullptr, nullptr);

    // Ht[g,d] = sum_f Wproj[g,f] Wv[f,d] : 3-MMA fold -> split fp16
    gemm_h<true,true><<<dim3(DIM/128, DIM/128, 1), blk, GEMM_SMEM>>>(
        wph, wpl, wvth, wvtl, nullptr, hth, htl,
        DIM, DIM, DIM, DIM, DIM, 0, 0, 0, 1.0f,
        nullptr, nullptr, nullptr);

    // q'[n,d'] = proto(split) @ Gt(single)^T : 2-MMA -> single fp16
    gemm_h<true,false><<<dim3(DIM/128, (BATCH*NQ)/128, 1), blk, GEMM_SMEM>>>(
        ph, pl, gth, nullptr, nullptr, qh, nullptr,
        BATCH*NQ, DIM, DIM, DIM, DIM, 0, 0, 0, 1.0f,
        nullptr, nullptr, nullptr);

    // attn[b] = scale * q'(single) @ xc(split)^T : 2-MMA -> fp32
    gemm_h<false,true><<<dim3(NKV/128, NQ/128, BATCH), blk, GEMM_SMEM>>>(
        qh, nullptr, xh, xl, attn, nullptr, nullptr,
        NQ, NKV, DIM, DIM, DIM,
        (size_t)NQ*DIM, (size_t)NKV*DIM, (size_t)NQ*NKV, scale,
        nullptr, cntp, nullptr);

    // softmax over compacted width -> single fp16 probs (0 in pad region)
    softmax_c_kernel<<<BATCH*NQ, 256>>>(attn, cnt, cntp, aph);

    // uT[b][g,m] = Ht(split) @ xc(split)^T : 3-MMA -> split fp16
    gemm_h<true,true><<<dim3(NKV/128, DIM/128, BATCH), blk, GEMM_SMEM>>>(
        hth, htl, xh, xl, nullptr, uth, utl,
        DIM, NKV, DIM, DIM, DIM,
        0, (size_t)NKV*DIM, (size_t)DIM*NKV, 1.0f,
        nullptr, cntp, nullptr);

    // out[b][n,g] = P(single) @ uT(split)^T : 2-MMA -> fp32
    gemm_h<false,true><<<dim3(DIM/128, NQ/128, BATCH), blk, GEMM_SMEM>>>(
        aph, nullptr, uth, utl, out, nullptr, nullptr,
        NQ, DIM, NKV, NKV, NKV,
        (size_t)NQ*NKV, (size_t)DIM*NKV, (size_t)NQ*DIM, 1.0f,
        nullptr, nullptr, cntp);
}

// round 14
// speedup vs baseline: 2.2879x; 1.5416x over previous
#include <cuda_runtime.h>
#include <cuda_fp16.h>
#include <cstdint>
#include <math.h>

#define BATCH 8
#define NQ    1024
#define NKV   4096
#define DIM   512

// ---------------- scratch (device globals: allocation-free) ----------------
__device__ __align__(16) __half s_ph [BATCH*NQ*DIM],  s_pl [BATCH*NQ*DIM];   // prototype split
__device__ __align__(16) __half s_xh [BATCH*NKV*DIM];                        // compacted q_x single
__device__ __align__(16) __half s_wqth[DIM*DIM], s_wqtl[DIM*DIM];            // Wq^T split
__device__ __align__(16) __half s_wkth[DIM*DIM], s_wktl[DIM*DIM];            // Wk^T split
__device__ __align__(16) __half s_wvth[DIM*DIM], s_wvtl[DIM*DIM];            // Wv^T split
__device__ __align__(16) __half s_wph [DIM*DIM], s_wpl [DIM*DIM];            // Wproj split
__device__ __align__(16) __half s_gth [DIM*DIM];                             // Gt single
__device__ __align__(16) __half s_hth [DIM*DIM];                             // Ht single
__device__ __align__(16) __half s_qh [BATCH*NQ*DIM];                         // q' single
__device__ __align__(16) __half s_uth[BATCH*DIM*NKV];                        // uT single
__device__ __align__(16) __half s_aph[(size_t)BATCH*NQ*NKV];                 // probs single
__device__ __align__(16) float g_attn[(size_t)BATCH*NQ*NKV];                 // scores fp32
__device__ int g_idx[BATCH*NKV];
__device__ int g_cnt[BATCH];
__device__ int g_cntp[BATCH];

// ============================================================================
// helpers
// ============================================================================
__device__ __forceinline__ uint32_t smem_u32(const void* p) {
    uint32_t a;
    asm("{ .reg .u64 t; cvta.to.shared.u64 t, %1; cvt.u32.u64 %0, t; }"
        : "=r"(a) : "l"(p));
    return a;
}
__device__ __forceinline__ void cp_async16(uint32_t saddr, const void* gaddr) {
    asm volatile("cp.async.ca.shared.global [%0], [%1], 16;"
                 :: "r"(saddr), "l"(gaddr) : "memory");
}
__device__ __forceinline__ void cp_commit() {
    asm volatile("cp.async.commit_group;" ::: "memory");
}
__device__ __forceinline__ void cp_wait1() {
    asm volatile("cp.async.wait_group 1;" ::: "memory");
}
__device__ __forceinline__ void cp_wait0() {
    asm volatile("cp.async.wait_group 0;" ::: "memory");
}

// mma.sync m16n8k16 fp16: d += a*b (f32 accumulators in-place)
__device__ __forceinline__ void mma_f16(float* d, const uint32_t* a, const uint32_t* b) {
    asm volatile(
        "mma.sync.aligned.m16n8k16.row.col.f32.f16.f16.f32 "
        "{%0,%1,%2,%3}, {%4,%5,%6,%7}, {%8,%9}, {%0,%1,%2,%3};"
        : "+f"(d[0]), "+f"(d[1]), "+f"(d[2]), "+f"(d[3])
        : "r"(a[0]), "r"(a[1]), "r"(a[2]), "r"(a[3]), "r"(b[0]), "r"(b[1]));
}

__device__ __forceinline__ void ldsm_x4(uint32_t& r0, uint32_t& r1,
                                        uint32_t& r2, uint32_t& r3, uint32_t addr) {
    asm volatile("ldmatrix.sync.aligned.m8n8.x4.shared.b16 {%0,%1,%2,%3}, [%4];"
                 : "=r"(r0), "=r"(r1), "=r"(r2), "=r"(r3) : "r"(addr));
}

// split (x,y) -> packed f16x2 hi + packed f16x2 lo residuals
__device__ __forceinline__ void pack_split(float x, float y, uint32_t& h, uint32_t& l) {
    __half2 hh = __float22half2_rn(make_float2(x, y));
    float2 hf = __half22float2(hh);
    __half2 ll = __float22half2_rn(make_float2(x - hf.x, y - hf.y));
    h = *reinterpret_cast<uint32_t*>(&hh);
    l = *reinterpret_cast<uint32_t*>(&ll);
}
__device__ __forceinline__ uint32_t pack_h(float x, float y) {
    __half2 hh = __float22half2_rn(make_float2(x, y));
    return *reinterpret_cast<uint32_t*>(&hh);
}

// ============================================================================
// mask scan: per batch, build compact index list of kept positions
// ============================================================================
__global__ void __launch_bounds__(1024) mask_scan_kernel(
    const int* __restrict__ mask, int* __restrict__ idx,
    int* __restrict__ cnt, int* __restrict__ cntp)
{
    const int b = blockIdx.x;
    const int t = threadIdx.x;
    const int* m = mask + b * NKV;
    __shared__ int sums[1024];

    int v[4], s = 0;
    #pragma unroll
    for (int i = 0; i < 4; i++) { v[i] = m[t * 4 + i] ? 1 : 0; s += v[i]; }
    sums[t] = s;
    __syncthreads();

    for (int off = 1; off < 1024; off <<= 1) {
        int x = (t >= off) ? sums[t - off] : 0;
        __syncthreads();
        sums[t] += x;
        __syncthreads();
    }

    int o = sums[t] - s;
    #pragma unroll
    for (int i = 0; i < 4; i++)
        if (v[i]) idx[b * NKV + o++] = t * 4 + i;

    if (t == 1023) {
        cnt[b]  = sums[1023];
        cntp[b] = (sums[1023] + 127) & ~127;
    }
}

// ============================================================================
// gather kept q_x rows (by idx) as single fp16; zero the pad rows.
// ============================================================================
__global__ void __launch_bounds__(128) gather_h_kernel(
    const float* __restrict__ qx, const int* __restrict__ idx,
    const int* __restrict__ cnt, const int* __restrict__ cntp,
    __half* __restrict__ xh)
{
    const int b = blockIdx.y;
    const int j = blockIdx.x;
    if (j >= cntp[b]) return;

    const size_t drow = ((size_t)b * NKV + j) * DIM;
    uint2* dh = (uint2*)(xh + drow) + threadIdx.x;

    if (j < cnt[b]) {
        const int r = idx[b * NKV + j];
        float4 vv = *((const float4*)(qx + ((size_t)b * NKV + r) * DIM) + threadIdx.x);
        *dh = make_uint2(pack_h(vv.x, vv.y), pack_h(vv.z, vv.w));
    } else {
        *dh = make_uint2(0u, 0u);
    }
}

// ============================================================================
// elementwise fp32 -> (hi, lo) fp16 split
// ============================================================================
__global__ void __launch_bounds__(256) split_kernel(
    const float* __restrict__ in, __half* __restrict__ h,
    __half* __restrict__ l, int n4)
{
    int i = blockIdx.x * 256 + threadIdx.x;
    if (i >= n4) return;
    float4 v = ((const float4*)in)[i];
    uint32_t h0, l0, h1, l1;
    pack_split(v.x, v.y, h0, l0);
    pack_split(v.z, v.w, h1, l1);
    ((uint2*)h)[i] = make_uint2(h0, h1);
    ((uint2*)l)[i] = make_uint2(l0, l1);
}

// ============================================================================
// transpose + split for 3 weight matrices: out[d,e] = in[e,d], fp16 hi/lo
// ============================================================================
__global__ void __launch_bounds__(1024) transpose_split3_kernel(
    const float* __restrict__ w0, const float* __restrict__ w1,
    const float* __restrict__ w2,
    __half* __restrict__ h0, __half* __restrict__ l0,
    __half* __restrict__ h1, __half* __restrict__ l1,
    __half* __restrict__ h2, __half* __restrict__ l2)
{
    __shared__ float tile[32][33];
    const int z = blockIdx.z;
    const float* in = z == 0 ? w0 : (z == 1 ? w1 : w2);
    __half* ho = z == 0 ? h0 : (z == 1 ? h1 : h2);
    __half* lo = z == 0 ? l0 : (z == 1 ? l1 : l2);

    int x = blockIdx.x * 32 + threadIdx.x;
    int y = blockIdx.y * 32 + threadIdx.y;
    tile[threadIdx.y][threadIdx.x] = in[y * DIM + x];
    __syncthreads();

    int ox = blockIdx.y * 32 + threadIdx.x;
    int oy = blockIdx.x * 32 + threadIdx.y;
    float v = tile[threadIdx.x][threadIdx.y];
    __half hb = __float2half_rn(v);
    float r = v - __half2float(hb);
    ho[oy * DIM + ox] = hb;
    lo[oy * DIM + ox] = __float2half_rn(r);
}

// ============================================================================
// fp16 split GEMM NT (round-9 engine), templated on operand splits:
//   C = alpha * (Ah [+Al]) @ (Bh [+Bl])^T
// MMAs per tile: ah*bh always; +al*bh if AS; +ah*bl if BS.
// 128 threads (4 warps, 2x2), warp tile 64x64, ldmatrix, 2-stage cp.async,
// 80B padded rows. Output: fp32 (Cf) | fp16 split (Ch,Cl) | fp16 single (Ch).
// ============================================================================
#define PAD2      40
#define ROW_B     (PAD2 * 2)               // 80 bytes per row
#define TILE_B    (128 * ROW_B)            // 10240
#define STAGE_B   (4 * TILE_B)             // 40960
#define GEMM_SMEM (2 * STAGE_B)            // 81920

template<bool AS, bool BS>
__global__ void __launch_bounds__(128, 2) gemm_h(
    const __half* __restrict__ Ah, const __half* __restrict__ Al,
    const __half* __restrict__ Bh, const __half* __restrict__ Bl,
    float* __restrict__ Cf,
    __half* __restrict__ Ch, __half* __restrict__ Cl,
    int M, int N, int K, int ldA, int ldB,
    size_t sA, size_t sB, size_t sC, float alpha,
    const int* __restrict__ mlim, const int* __restrict__ nlim,
    const int* __restrict__ kdyn)
{
    extern __shared__ __align__(16) char smem[];
    const uint32_t sbase = smem_u32(smem);

    const int m0 = blockIdx.y * 128;
    const int n0 = blockIdx.x * 128;
    if (mlim && m0 >= mlim[blockIdx.z]) return;
    if (nlim && n0 >= nlim[blockIdx.z]) return;
    if (kdyn) K = kdyn[blockIdx.z];

    const int t    = threadIdx.x;
    const int wid  = t >> 5;
    const int lane = t & 31;
    const int g    = lane >> 2;
    const int c    = lane & 3;
    const int warp_m = wid >> 1;    // 0..1
    const int warp_n = wid & 1;     // 0..1

    const uint32_t a_row = lane & 15;
    const uint32_t a_kh  = (lane >> 4) * 16;
    const uint32_t b_row = (lane & 7) + ((lane >> 4) << 3);
    const uint32_t b_kh  = ((lane >> 3) & 1) * 16;

    Ah += (size_t)blockIdx.z * sA;
    Bh += (size_t)blockIdx.z * sB;
    if (AS) Al += (size_t)blockIdx.z * sA;
    if (BS) Bl += (size_t)blockIdx.z * sB;

    auto load_tile = [&](int kt, int s) {
        const uint32_t st = sbase + (uint32_t)(s * STAGE_B);
        const int kb = kt * 32;
        #pragma unroll
        for (int ph = 0; ph < 4; ph++) {
            int idx = ph * 128 + t;
            int row = idx >> 2;
            int c4  = idx & 3;
            uint32_t so = (uint32_t)(row * ROW_B + c4 * 16);
            const size_t ga = (size_t)(m0 + row) * ldA + kb + c4 * 8;
            const size_t gb = (size_t)(n0 + row) * ldB + kb + c4 * 8;
            cp_async16(st + 0 * TILE_B + so, Ah + ga);
            if (AS) cp_async16(st + 1 * TILE_B + so, Al + ga);
            cp_async16(st + 2 * TILE_B + so, Bh + gb);
            if (BS) cp_async16(st + 3 * TILE_B + so, Bl + gb);
        }
        cp_commit();
    };

    float acc[4][8][4] = {};

    const int nkt = K >> 5;
    load_tile(0, 0);

    for (int kt = 0; kt < nkt; kt++) {
        const int s = kt & 1;
        if (kt + 1 < nkt) {
            load_tile(kt + 1, s ^ 1);
            cp_wait1();
        } else {
            cp_wait0();
        }
        __syncthreads();

        const uint32_t aB = sbase + s * STAGE_B + warp_m * 64 * ROW_B;
        const uint32_t bB = sbase + s * STAGE_B + 2 * TILE_B + warp_n * 64 * ROW_B;

        #pragma unroll
        for (int ks2 = 0; ks2 < 2; ks2++) {
            const uint32_t kso = ks2 * 32;

            uint32_t bh[8][2], bl[8][2];
            #pragma unroll
            for (int p = 0; p < 4; p++) {
                uint32_t addr = bB + (p * 16 + b_row) * ROW_B + kso + b_kh;
                ldsm_x4(bh[2*p][0], bh[2*p][1], bh[2*p+1][0], bh[2*p+1][1], addr);
                if (BS)
                    ldsm_x4(bl[2*p][0], bl[2*p][1], bl[2*p+1][0], bl[2*p+1][1],
                            addr + TILE_B);
            }

            #pragma unroll
            for (int mt = 0; mt < 4; mt++) {
                uint32_t addr = aB + (mt * 16 + a_row) * ROW_B + kso + a_kh;
                uint32_t ah[4], al[4];
                ldsm_x4(ah[0], ah[1], ah[2], ah[3], addr);
                if (AS)
                    ldsm_x4(al[0], al[1], al[2], al[3], addr + TILE_B);
                #pragma unroll
                for (int nt = 0; nt < 8; nt++) {
                    if (AS) mma_f16(acc[mt][nt], al, bh[nt]);   // small terms first
                    if (BS) mma_f16(acc[mt][nt], ah, bl[nt]);
                    mma_f16(acc[mt][nt], ah, bh[nt]);
                }
            }
        }
        __syncthreads();
    }

    if (Cf) {
        Cf += (size_t)blockIdx.z * sC;
        #pragma unroll
        for (int mt = 0; mt < 4; mt++) {
            const int row = m0 + warp_m * 64 + mt * 16 + g;
            #pragma unroll
            for (int nt = 0; nt < 8; nt++) {
                const int col = n0 + warp_n * 64 + nt * 8 + 2 * c;
                *(float2*)(Cf + (size_t)row * N + col) =
                    make_float2(acc[mt][nt][0] * alpha, acc[mt][nt][1] * alpha);
                *(float2*)(Cf + (size_t)(row + 8) * N + col) =
                    make_float2(acc[mt][nt][2] * alpha, acc[mt][nt][3] * alpha);
            }
        }
    } else if (Cl) {
        Ch += (size_t)blockIdx.z * sC;
        Cl += (size_t)blockIdx.z * sC;
        #pragma unroll
        for (int mt = 0; mt < 4; mt++) {
            const int row = m0 + warp_m * 64 + mt * 16 + g;
            #pragma unroll
            for (int nt = 0; nt < 8; nt++) {
                const int col = n0 + warp_n * 64 + nt * 8 + 2 * c;
                uint32_t h, l;
                pack_split(acc[mt][nt][0] * alpha, acc[mt][nt][1] * alpha, h, l);
                *(uint32_t*)(Ch + (size_t)row * N + col) = h;
                *(uint32_t*)(Cl + (size_t)row * N + col) = l;
                pack_split(acc[mt][nt][2] * alpha, acc[mt][nt][3] * alpha, h, l);
                *(uint32_t*)(Ch + (size_t)(row + 8) * N + col) = h;
                *(uint32_t*)(Cl + (size_t)(row + 8) * N + col) = l;
            }
        }
    } else {
        Ch += (size_t)blockIdx.z * sC;
        #pragma unroll
        for (int mt = 0; mt < 4; mt++) {
            const int row = m0 + warp_m * 64 + mt * 16 + g;
            #pragma unroll
            for (int nt = 0; nt < 8; nt++) {
                const int col = n0 + warp_n * 64 + nt * 8 + 2 * c;
                *(uint32_t*)(Ch + (size_t)row * N + col) =
                    pack_h(acc[mt][nt][0] * alpha, acc[mt][nt][1] * alpha);
                *(uint32_t*)(Ch + (size_t)(row + 8) * N + col) =
                    pack_h(acc[mt][nt][2] * alpha, acc[mt][nt][3] * alpha);
            }
        }
    }
}

// ============================================================================
// softmax over compacted scores -> single fp16 probs (pad region = 0).
// ============================================================================
__global__ void __launch_bounds__(256) softmax_c_kernel(
    const float* __restrict__ attn, const int* __restrict__ cnt,
    const int* __restrict__ cntp, __half* __restrict__ Ph)
{
    const int row = blockIdx.x;
    const int b   = row >> 10;             // NQ = 1024
    const int cn  = cnt[b];
    const int cp  = cntp[b];
    const float2* p = (const float2*)(attn + (size_t)row * NKV);

    float2 v[8];
    float mx = -3.0e38f;
    #pragma unroll
    for (int i = 0; i < 8; i++) {
        int j2 = threadIdx.x + i * 256;
        int j  = 2 * j2;
        float2 x = make_float2(-3.0e38f, -3.0e38f);
        if (j < cp) {
            x = p[j2];
            if (j     >= cn) x.x = -3.0e38f;
            if (j + 1 >= cn) x.y = -3.0e38f;
        }
        v[i] = x;
        mx = fmaxf(mx, fmaxf(x.x, x.y));
    }

    __shared__ float red[8];
    #pragma unroll
    for (int o = 16; o; o >>= 1) mx = fmaxf(mx, __shfl_xor_sync(0xffffffffu, mx, o));
    if ((threadIdx.x & 31) == 0) red[threadIdx.x >> 5] = mx;
    __syncthreads();
    float bm = red[0];
    #pragma unroll
    for (int w = 1; w < 8; w++) bm = fmaxf(bm, red[w]);
    __syncthreads();

    float sum = 0.0f;
    #pragma unroll
    for (int i = 0; i < 8; i++) {
        v[i].x = __expf(v[i].x - bm);
        v[i].y = __expf(v[i].y - bm);
        sum += v[i].x + v[i].y;
    }
    #pragma unroll
    for (int o = 16; o; o >>= 1) sum += __shfl_xor_sync(0xffffffffu, sum, o);
    if ((threadIdx.x & 31) == 0) red[threadIdx.x >> 5] = sum;
    __syncthreads();
    float ts = red[0];
    #pragma unroll
    for (int w = 1; w < 8; w++) ts += red[w];
    float inv = 1.0f / ts;

    #pragma unroll
    for (int i = 0; i < 8; i++) {
        int j2 = threadIdx.x + i * 256;
        int j  = 2 * j2;
        if (j < cp)
            *(uint32_t*)(Ph + (size_t)row * NKV + j) =
                pack_h(v[i].x * inv, v[i].y * inv);
    }
}

// ============================================================================
// launch
// ============================================================================
extern "C" void kernel_launch(void* const* d_in, const int* in_sizes, int n_in,
                              void* d_out, int out_size)
{
    const float* prototype = (const float*)d_in[0];
    const float* q_x       = (const float*)d_in[1];
    const int*   mask      = (const int*)  d_in[2];
    const float* Wq        = (const float*)d_in[3];
    const float* Wk        = (const float*)d_in[4];
    const float* Wv        = (const float*)d_in[5];
    const float* Wproj     = (const float*)d_in[6];
    float* out = (float*)d_out;

    __half *ph, *pl, *xh, *wqth, *wqtl, *wkth, *wktl, *wvth, *wvtl,
           *wph, *wpl, *gth, *hth, *qh, *uth, *aph;
    float* attn;
    int *idx, *cnt, *cntp;
    cudaGetSymbolAddress((void**)&ph,   s_ph);   cudaGetSymbolAddress((void**)&pl,   s_pl);
    cudaGetSymbolAddress((void**)&xh,   s_xh);
    cudaGetSymbolAddress((void**)&wqth, s_wqth); cudaGetSymbolAddress((void**)&wqtl, s_wqtl);
    cudaGetSymbolAddress((void**)&wkth, s_wkth); cudaGetSymbolAddress((void**)&wktl, s_wktl);
    cudaGetSymbolAddress((void**)&wvth, s_wvth); cudaGetSymbolAddress((void**)&wvtl, s_wvtl);
    cudaGetSymbolAddress((void**)&wph,  s_wph);  cudaGetSymbolAddress((void**)&wpl,  s_wpl);
    cudaGetSymbolAddress((void**)&gth,  s_gth);
    cudaGetSymbolAddress((void**)&hth,  s_hth);
    cudaGetSymbolAddress((void**)&qh,   s_qh);
    cudaGetSymbolAddress((void**)&uth,  s_uth);
    cudaGetSymbolAddress((void**)&aph,  s_aph);
    cudaGetSymbolAddress((void**)&attn, g_attn);
    cudaGetSymbolAddress((void**)&idx,  g_idx);
    cudaGetSymbolAddress((void**)&cnt,  g_cnt);
    cudaGetSymbolAddress((void**)&cntp, g_cntp);

    cudaFuncSetAttribute(gemm_h<true,true>,
                         cudaFuncAttributeMaxDynamicSharedMemorySize, GEMM_SMEM);
    cudaFuncSetAttribute(gemm_h<true,false>,
                         cudaFuncAttributeMaxDynamicSharedMemorySize, GEMM_SMEM);
    cudaFuncSetAttribute(gemm_h<false,false>,
                         cudaFuncAttributeMaxDynamicSharedMemorySize, GEMM_SMEM);

    const float scale = 0.04419417382415922f;  // 1/sqrt(512)
    dim3 blk(128);

    // mask scan + gather of kept q_x rows (single fp16)
    mask_scan_kernel<<<BATCH, 1024>>>(mask, idx, cnt, cntp);
    gather_h_kernel<<<dim3(NKV, BATCH), 128>>>(q_x, idx, cnt, cntp, xh);

    // splits: prototype, Wproj (plain); Wq, Wk, Wv (transposed)
    split_kernel<<<(BATCH*NQ*DIM/4 + 255)/256, 256>>>(prototype, ph, pl, BATCH*NQ*DIM/4);
    split_kernel<<<(DIM*DIM/4 + 255)/256, 256>>>(Wproj, wph, wpl, DIM*DIM/4);
    transpose_split3_kernel<<<dim3(16, 16, 3), dim3(32, 32)>>>(
        Wq, Wk, Wv, wqth, wqtl, wkth, wktl, wvth, wvtl);

    // Gt[d',d] = sum_e Wk[e,d'] Wq[e,d] : 3-MMA fold -> single fp16
    gemm_h<true,true><<<dim3(DIM/128, DIM/128, 1), blk, GEMM_SMEM>>>(
        wkth, wktl, wqth, wqtl, nullptr, gth, nullptr,
        DIM, DIM, DIM, DIM, DIM, 0, 0, 0, 1.0f,
        nullptr, nullptr, nullptr);

    // Ht[g,d] = sum_f Wproj[g,f] Wv[f,d] : 3-MMA fold -> single fp16
    gemm_h<true,true><<<dim3(DIM/128, DIM/128, 1), blk, GEMM_SMEM>>>(
        wph, wpl, wvth, wvtl, nullptr, hth, nullptr,
        DIM, DIM, DIM, DIM, DIM, 0, 0, 0, 1.0f,
        nullptr, nullptr, nullptr);

    // q'[n,d'] = proto(split) @ Gt(single)^T : 2-MMA -> single fp16
    gemm_h<true,false><<<dim3(DIM/128, (BATCH*NQ)/128, 1), blk, GEMM_SMEM>>>(
        ph, pl, gth, nullptr, nullptr, qh, nullptr,
        BATCH*NQ, DIM, DIM, DIM, DIM, 0, 0, 0, 1.0f,
        nullptr, nullptr, nullptr);

    // attn[b] = scale * q'(single) @ xc(single)^T : 1-MMA -> fp32
    gemm_h<false,false><<<dim3(NKV/128, NQ/128, BATCH), blk, GEMM_SMEM>>>(
        qh, nullptr, xh, nullptr, attn, nullptr, nullptr,
        NQ, NKV, DIM, DIM, DIM,
        (size_t)NQ*DIM, (size_t)NKV*DIM, (size_t)NQ*NKV, scale,
        nullptr, cntp, nullptr);

    // softmax over compacted width -> single fp16 probs (0 in pad region)
    softmax_c_kernel<<<BATCH*NQ, 256>>>(attn, cnt, cntp, aph);

    // uT[b][g,m] = Ht(single) @ xc(single)^T : 1-MMA -> single fp16
    gemm_h<false,false><<<dim3(NKV/128, DIM/128, BATCH), blk, GEMM_SMEM>>>(
        hth, nullptr, xh, nullptr, nullptr, uth, nullptr,
        DIM, NKV, DIM, DIM, DIM,
        0, (size_t)NKV*DIM, (size_t)DIM*NKV, 1.0f,
        nullptr, cntp, nullptr);

    // out[b][n,g] = P(single) @ uT(single)^T : 1-MMA -> fp32
    gemm_h<false,false><<<dim3(DIM/128, NQ/128, BATCH), blk, GEMM_SMEM>>>(
        aph, nullptr, uth, nullptr, out, nullptr, nullptr,
        NQ, DIM, NKV, NKV, NKV,
        (size_t)NQ*NKV, (size_t)DIM*NKV, (size_t)NQ*DIM, 1.0f,
        nullptr, nullptr, cntp);
}

// round 15
// speedup vs baseline: 2.5573x; 1.1178x over previous
#include <cuda_runtime.h>
#include <cuda_fp16.h>
#include <cstdint>
#include <math.h>

#define BATCH 8
#define NQ    1024
#define NKV   4096
#define DIM   512

// ---------------- scratch (device globals: allocation-free) ----------------
__device__ __align__(16) __half s_ph [BATCH*NQ*DIM],  s_pl [BATCH*NQ*DIM];   // prototype split
__device__ __align__(16) __half s_xh [BATCH*NKV*DIM];                        // compacted q_x single
__device__ __align__(16) __half s_wqth[DIM*DIM], s_wqtl[DIM*DIM];            // Wq^T split
__device__ __align__(16) __half s_wkth[DIM*DIM], s_wktl[DIM*DIM];            // Wk^T split
__device__ __align__(16) __half s_wvth[DIM*DIM], s_wvtl[DIM*DIM];            // Wv^T split
__device__ __align__(16) __half s_wph [DIM*DIM], s_wpl [DIM*DIM];            // Wproj split
__device__ __align__(16) __half s_gth [DIM*DIM];                             // Gt single
__device__ __align__(16) __half s_hth [DIM*DIM];                             // Ht single
__device__ __align__(16) __half s_qh [BATCH*NQ*DIM];                         // q' single
__device__ __align__(16) __half s_uth[BATCH*DIM*NKV];                        // uT single
__device__ __align__(16) __half s_aph[(size_t)BATCH*NQ*NKV];                 // logits->probs fp16
__device__ int g_idx[BATCH*NKV];
__device__ int g_cnt[BATCH];
__device__ int g_cntp[BATCH];

// ============================================================================
// helpers
// ============================================================================
__device__ __forceinline__ uint32_t smem_u32(const void* p) {
    uint32_t a;
    asm("{ .reg .u64 t; cvta.to.shared.u64 t, %1; cvt.u32.u64 %0, t; }"
        : "=r"(a) : "l"(p));
    return a;
}
__device__ __forceinline__ void cp_async16(uint32_t saddr, const void* gaddr) {
    asm volatile("cp.async.ca.shared.global [%0], [%1], 16;"
                 :: "r"(saddr), "l"(gaddr) : "memory");
}
__device__ __forceinline__ void cp_commit() {
    asm volatile("cp.async.commit_group;" ::: "memory");
}
__device__ __forceinline__ void cp_wait1() {
    asm volatile("cp.async.wait_group 1;" ::: "memory");
}
__device__ __forceinline__ void cp_wait0() {
    asm volatile("cp.async.wait_group 0;" ::: "memory");
}

// mma.sync m16n8k16 fp16: d += a*b (f32 accumulators in-place)
__device__ __forceinline__ void mma_f16(float* d, const uint32_t* a, const uint32_t* b) {
    asm volatile(
        "mma.sync.aligned.m16n8k16.row.col.f32.f16.f16.f32 "
        "{%0,%1,%2,%3}, {%4,%5,%6,%7}, {%8,%9}, {%0,%1,%2,%3};"
        : "+f"(d[0]), "+f"(d[1]), "+f"(d[2]), "+f"(d[3])
        : "r"(a[0]), "r"(a[1]), "r"(a[2]), "r"(a[3]), "r"(b[0]), "r"(b[1]));
}

__device__ __forceinline__ void ldsm_x4(uint32_t& r0, uint32_t& r1,
                                        uint32_t& r2, uint32_t& r3, uint32_t addr) {
    asm volatile("ldmatrix.sync.aligned.m8n8.x4.shared.b16 {%0,%1,%2,%3}, [%4];"
                 : "=r"(r0), "=r"(r1), "=r"(r2), "=r"(r3) : "r"(addr));
}

// split (x,y) -> packed f16x2 hi + packed f16x2 lo residuals
__device__ __forceinline__ void pack_split(float x, float y, uint32_t& h, uint32_t& l) {
    __half2 hh = __float22half2_rn(make_float2(x, y));
    float2 hf = __half22float2(hh);
    __half2 ll = __float22half2_rn(make_float2(x - hf.x, y - hf.y));
    h = *reinterpret_cast<uint32_t*>(&hh);
    l = *reinterpret_cast<uint32_t*>(&ll);
}
__device__ __forceinline__ uint32_t pack_h(float x, float y) {
    __half2 hh = __float22half2_rn(make_float2(x, y));
    return *reinterpret_cast<uint32_t*>(&hh);
}

// ============================================================================
// mask scan: per batch, build compact index list of kept positions
// ============================================================================
__global__ void __launch_bounds__(1024) mask_scan_kernel(
    const int* __restrict__ mask, int* __restrict__ idx,
    int* __restrict__ cnt, int* __restrict__ cntp)
{
    const int b = blockIdx.x;
    const int t = threadIdx.x;
    const int* m = mask + b * NKV;
    __shared__ int sums[1024];

    int v[4], s = 0;
    #pragma unroll
    for (int i = 0; i < 4; i++) { v[i] = m[t * 4 + i] ? 1 : 0; s += v[i]; }
    sums[t] = s;
    __syncthreads();

    for (int off = 1; off < 1024; off <<= 1) {
        int x = (t >= off) ? sums[t - off] : 0;
        __syncthreads();
        sums[t] += x;
        __syncthreads();
    }

    int o = sums[t] - s;
    #pragma unroll
    for (int i = 0; i < 4; i++)
        if (v[i]) idx[b * NKV + o++] = t * 4 + i;

    if (t == 1023) {
        cnt[b]  = sums[1023];
        cntp[b] = (sums[1023] + 127) & ~127;
    }
}

// ============================================================================
// gather kept q_x rows (by idx) as single fp16; zero the pad rows.
// ============================================================================
__global__ void __launch_bounds__(128) gather_h_kernel(
    const float* __restrict__ qx, const int* __restrict__ idx,
    const int* __restrict__ cnt, const int* __restrict__ cntp,
    __half* __restrict__ xh)
{
    const int b = blockIdx.y;
    const int j = blockIdx.x;
    if (j >= cntp[b]) return;

    const size_t drow = ((size_t)b * NKV + j) * DIM;
    uint2* dh = (uint2*)(xh + drow) + threadIdx.x;

    if (j < cnt[b]) {
        const int r = idx[b * NKV + j];
        float4 vv = *((const float4*)(qx + ((size_t)b * NKV + r) * DIM) + threadIdx.x);
        *dh = make_uint2(pack_h(vv.x, vv.y), pack_h(vv.z, vv.w));
    } else {
        *dh = make_uint2(0u, 0u);
    }
}

// ============================================================================
// elementwise fp32 -> (hi, lo) fp16 split
// ============================================================================
__global__ void __launch_bounds__(256) split_kernel(
    const float* __restrict__ in, __half* __restrict__ h,
    __half* __restrict__ l, int n4)
{
    int i = blockIdx.x * 256 + threadIdx.x;
    if (i >= n4) return;
    float4 v = ((const float4*)in)[i];
    uint32_t h0, l0, h1, l1;
    pack_split(v.x, v.y, h0, l0);
    pack_split(v.z, v.w, h1, l1);
    ((uint2*)h)[i] = make_uint2(h0, h1);
    ((uint2*)l)[i] = make_uint2(l0, l1);
}

// ============================================================================
// transpose + split for 3 weight matrices: out[d,e] = in[e,d], fp16 hi/lo
// ============================================================================
__global__ void __launch_bounds__(1024) transpose_split3_kernel(
    const float* __restrict__ w0, const float* __restrict__ w1,
    const float* __restrict__ w2,
    __half* __restrict__ h0, __half* __restrict__ l0,
    __half* __restrict__ h1, __half* __restrict__ l1,
    __half* __restrict__ h2, __half* __restrict__ l2)
{
    __shared__ float tile[32][33];
    const int z = blockIdx.z;
    const float* in = z == 0 ? w0 : (z == 1 ? w1 : w2);
    __half* ho = z == 0 ? h0 : (z == 1 ? h1 : h2);
    __half* lo = z == 0 ? l0 : (z == 1 ? l1 : l2);

    int x = blockIdx.x * 32 + threadIdx.x;
    int y = blockIdx.y * 32 + threadIdx.y;
    tile[threadIdx.y][threadIdx.x] = in[y * DIM + x];
    __syncthreads();

    int ox = blockIdx.y * 32 + threadIdx.x;
    int oy = blockIdx.x * 32 + threadIdx.y;
    float v = tile[threadIdx.x][threadIdx.y];
    __half hb = __float2half_rn(v);
    float r = v - __half2float(hb);
    ho[oy * DIM + ox] = hb;
    lo[oy * DIM + ox] = __float2half_rn(r);
}

// ============================================================================
// fp16 split GEMM core (round-9 engine): 128 threads (4 warps, 2x2),
// warp tile 64x64, ldmatrix, 2-stage cp.async, 80B padded rows.
//   C = alpha * (Ah [+Al]) @ (Bh [+Bl])^T ; MMAs: ah*bh [+al*bh if AS] [+ah*bl if BS]
// Pointers are pre-offset for batch; N is the output leading dim.
// Output: fp32 (Cf) | fp16 split (Ch,Cl) | fp16 single (Ch).
// ============================================================================
#define PAD2      40
#define ROW_B     (PAD2 * 2)               // 80 bytes per row
#define TILE_B    (128 * ROW_B)            // 10240
#define STAGE_B   (4 * TILE_B)             // 40960
#define GEMM_SMEM (2 * STAGE_B)            // 81920

template<bool AS, bool BS>
__device__ __forceinline__ void gemm_core(
    const __half* __restrict__ Ah, const __half* __restrict__ Al,
    const __half* __restrict__ Bh, const __half* __restrict__ Bl,
    float* __restrict__ Cf, __half* __restrict__ Ch, __half* __restrict__ Cl,
    int N, int K, int ldA, int ldB, float alpha,
    uint32_t sbase, int m0, int n0)
{
    const int t    = threadIdx.x;
    const int wid  = t >> 5;
    const int lane = t & 31;
    const int g    = lane >> 2;
    const int c    = lane & 3;
    const int warp_m = wid >> 1;    // 0..1
    const int warp_n = wid & 1;     // 0..1

    const uint32_t a_row = lane & 15;
    const uint32_t a_kh  = (lane >> 4) * 16;
    const uint32_t b_row = (lane & 7) + ((lane >> 4) << 3);
    const uint32_t b_kh  = ((lane >> 3) & 1) * 16;

    auto load_tile = [&](int kt, int s) {
        const uint32_t st = sbase + (uint32_t)(s * STAGE_B);
        const int kb = kt * 32;
        #pragma unroll
        for (int ph = 0; ph < 4; ph++) {
            int idx = ph * 128 + t;
            int row = idx >> 2;
            int c4  = idx & 3;
            uint32_t so = (uint32_t)(row * ROW_B + c4 * 16);
            const size_t ga = (size_t)(m0 + row) * ldA + kb + c4 * 8;
            const size_t gb = (size_t)(n0 + row) * ldB + kb + c4 * 8;
            cp_async16(st + 0 * TILE_B + so, Ah + ga);
            if (AS) cp_async16(st + 1 * TILE_B + so, Al + ga);
            cp_async16(st + 2 * TILE_B + so, Bh + gb);
            if (BS) cp_async16(st + 3 * TILE_B + so, Bl + gb);
        }
        cp_commit();
    };

    float acc[4][8][4] = {};

    const int nkt = K >> 5;
    load_tile(0, 0);

    for (int kt = 0; kt < nkt; kt++) {
        const int s = kt & 1;
        if (kt + 1 < nkt) {
            load_tile(kt + 1, s ^ 1);
            cp_wait1();
        } else {
            cp_wait0();
        }
        __syncthreads();

        const uint32_t aB = sbase + s * STAGE_B + warp_m * 64 * ROW_B;
        const uint32_t bB = sbase + s * STAGE_B + 2 * TILE_B + warp_n * 64 * ROW_B;

        #pragma unroll
        for (int ks2 = 0; ks2 < 2; ks2++) {
            const uint32_t kso = ks2 * 32;

            uint32_t bh[8][2], bl[8][2];
            #pragma unroll
            for (int p = 0; p < 4; p++) {
                uint32_t addr = bB + (p * 16 + b_row) * ROW_B + kso + b_kh;
                ldsm_x4(bh[2*p][0], bh[2*p][1], bh[2*p+1][0], bh[2*p+1][1], addr);
                if (BS)
                    ldsm_x4(bl[2*p][0], bl[2*p][1], bl[2*p+1][0], bl[2*p+1][1],
                            addr + TILE_B);
            }

            #pragma unroll
            for (int mt = 0; mt < 4; mt++) {
                uint32_t addr = aB + (mt * 16 + a_row) * ROW_B + kso + a_kh;
                uint32_t ah[4], al[4];
                ldsm_x4(ah[0], ah[1], ah[2], ah[3], addr);
                if (AS)
                    ldsm_x4(al[0], al[1], al[2], al[3], addr + TILE_B);
                #pragma unroll
                for (int nt = 0; nt < 8; nt++) {
                    if (AS) mma_f16(acc[mt][nt], al, bh[nt]);   // small terms first
                    if (BS) mma_f16(acc[mt][nt], ah, bl[nt]);
                    mma_f16(acc[mt][nt], ah, bh[nt]);
                }
            }
        }
        __syncthreads();
    }

    if (Cf) {
        #pragma unroll
        for (int mt = 0; mt < 4; mt++) {
            const int row = m0 + warp_m * 64 + mt * 16 + g;
            #pragma unroll
            for (int nt = 0; nt < 8; nt++) {
                const int col = n0 + warp_n * 64 + nt * 8 + 2 * c;
                *(float2*)(Cf + (size_t)row * N + col) =
                    make_float2(acc[mt][nt][0] * alpha, acc[mt][nt][1] * alpha);
                *(float2*)(Cf + (size_t)(row + 8) * N + col) =
                    make_float2(acc[mt][nt][2] * alpha, acc[mt][nt][3] * alpha);
            }
        }
    } else if (Cl) {
        #pragma unroll
        for (int mt = 0; mt < 4; mt++) {
            const int row = m0 + warp_m * 64 + mt * 16 + g;
            #pragma unroll
            for (int nt = 0; nt < 8; nt++) {
                const int col = n0 + warp_n * 64 + nt * 8 + 2 * c;
                uint32_t h, l;
                pack_split(acc[mt][nt][0] * alpha, acc[mt][nt][1] * alpha, h, l);
                *(uint32_t*)(Ch + (size_t)row * N + col) = h;
                *(uint32_t*)(Cl + (size_t)row * N + col) = l;
                pack_split(acc[mt][nt][2] * alpha, acc[mt][nt][3] * alpha, h, l);
                *(uint32_t*)(Ch + (size_t)(row + 8) * N + col) = h;
                *(uint32_t*)(Cl + (size_t)(row + 8) * N + col) = l;
            }
        }
    } else {
        #pragma unroll
        for (int mt = 0; mt < 4; mt++) {
            const int row = m0 + warp_m * 64 + mt * 16 + g;
            #pragma unroll
            for (int nt = 0; nt < 8; nt++) {
                const int col = n0 + warp_n * 64 + nt * 8 + 2 * c;
                *(uint32_t*)(Ch + (size_t)row * N + col) =
                    pack_h(acc[mt][nt][0] * alpha, acc[mt][nt][1] * alpha);
                *(uint32_t*)(Ch + (size_t)(row + 8) * N + col) =
                    pack_h(acc[mt][nt][2] * alpha, acc[mt][nt][3] * alpha);
            }
        }
    }
}

template<bool AS, bool BS>
__global__ void __launch_bounds__(128, 2) gemm_h(
    const __half* __restrict__ Ah, const __half* __restrict__ Al,
    const __half* __restrict__ Bh, const __half* __restrict__ Bl,
    float* __restrict__ Cf,
    __half* __restrict__ Ch, __half* __restrict__ Cl,
    int M, int N, int K, int ldA, int ldB,
    size_t sA, size_t sB, size_t sC, float alpha,
    const int* __restrict__ mlim, const int* __restrict__ nlim,
    const int* __restrict__ kdyn)
{
    extern __shared__ __align__(16) char smem[];
    const uint32_t sbase = smem_u32(smem);

    const int m0 = blockIdx.y * 128;
    const int n0 = blockIdx.x * 128;
    if (mlim && m0 >= mlim[blockIdx.z]) return;
    if (nlim && n0 >= nlim[blockIdx.z]) return;
    if (kdyn) K = kdyn[blockIdx.z];

    Ah += (size_t)blockIdx.z * sA;
    Bh += (size_t)blockIdx.z * sB;
    if (AS) Al += (size_t)blockIdx.z * sA;
    if (BS) Bl += (size_t)blockIdx.z * sB;
    if (Cf) Cf += (size_t)blockIdx.z * sC;
    if (Ch) Ch += (size_t)blockIdx.z * sC;
    if (Cl) Cl += (size_t)blockIdx.z * sC;

    gemm_core<AS, BS>(Ah, Al, Bh, Bl, Cf, Ch, Cl,
                      N, K, ldA, ldB, alpha, sbase, m0, n0);
}

// both 512x512x512 weight folds in ONE launch: blockIdx.z selects the fold
__global__ void __launch_bounds__(128, 2) fold2_kernel(
    const __half* __restrict__ a0h, const __half* __restrict__ a0l,
    const __half* __restrict__ b0h, const __half* __restrict__ b0l,
    __half* __restrict__ c0,
    const __half* __restrict__ a1h, const __half* __restrict__ a1l,
    const __half* __restrict__ b1h, const __half* __restrict__ b1l,
    __half* __restrict__ c1)
{
    extern __shared__ __align__(16) char smem[];
    const uint32_t sbase = smem_u32(smem);
    const int m0 = blockIdx.y * 128;
    const int n0 = blockIdx.x * 128;
    const bool z = blockIdx.z != 0;
    gemm_core<true, true>(z ? a1h : a0h, z ? a1l : a0l,
                          z ? b1h : b0h, z ? b1l : b0l,
                          nullptr, z ? c1 : c0, nullptr,
                          DIM, DIM, DIM, DIM, 1.0f, sbase, m0, n0);
}

// ============================================================================
// softmax in place on fp16 logits -> fp16 probs; row width cnt[b], pad to cntp.
// ============================================================================
__global__ void __launch_bounds__(256) softmax_h_kernel(
    __half* __restrict__ P, const int* __restrict__ cnt,
    const int* __restrict__ cntp)
{
    const int row = blockIdx.x;
    const int b   = row >> 10;             // NQ = 1024
    const int cn  = cnt[b];
    const int cp  = cntp[b];
    uint32_t* p = (uint32_t*)(P + (size_t)row * NKV);

    float2 v[8];
    float mx = -3.0e38f;
    #pragma unroll
    for (int i = 0; i < 8; i++) {
        int j2 = threadIdx.x + i * 256;
        int j  = 2 * j2;
        float2 x = make_float2(-3.0e38f, -3.0e38f);
        if (j < cp) {
            uint32_t w = p[j2];
            __half2 hv = *reinterpret_cast<__half2*>(&w);
            x = __half22float2(hv);
            if (j     >= cn) x.x = -3.0e38f;
            if (j + 1 >= cn) x.y = -3.0e38f;
        }
        v[i] = x;
        mx = fmaxf(mx, fmaxf(x.x, x.y));
    }

    __shared__ float red[8];
    #pragma unroll
    for (int o = 16; o; o >>= 1) mx = fmaxf(mx, __shfl_xor_sync(0xffffffffu, mx, o));
    if ((threadIdx.x & 31) == 0) red[threadIdx.x >> 5] = mx;
    __syncthreads();
    float bm = red[0];
    #pragma unroll
    for (int w = 1; w < 8; w++) bm = fmaxf(bm, red[w]);
    __syncthreads();

    float sum = 0.0f;
    #pragma unroll
    for (int i = 0; i < 8; i++) {
        v[i].x = __expf(v[i].x - bm);
        v[i].y = __expf(v[i].y - bm);
        sum += v[i].x + v[i].y;
    }
    #pragma unroll
    for (int o = 16; o; o >>= 1) sum += __shfl_xor_sync(0xffffffffu, sum, o);
    if ((threadIdx.x & 31) == 0) red[threadIdx.x >> 5] = sum;
    __syncthreads();
    float ts = red[0];
    #pragma unroll
    for (int w = 1; w < 8; w++) ts += red[w];
    float inv = 1.0f / ts;

    #pragma unroll
    for (int i = 0; i < 8; i++) {
        int j2 = threadIdx.x + i * 256;
        int j  = 2 * j2;
        if (j < cp)
            p[j2] = pack_h(v[i].x * inv, v[i].y * inv);
    }
}

// ============================================================================
// launch
// ============================================================================
extern "C" void kernel_launch(void* const* d_in, const int* in_sizes, int n_in,
                              void* d_out, int out_size)
{
    const float* prototype = (const float*)d_in[0];
    const float* q_x       = (const float*)d_in[1];
    const int*   mask      = (const int*)  d_in[2];
    const float* Wq        = (const float*)d_in[3];
    const float* Wk        = (const float*)d_in[4];
    const float* Wv        = (const float*)d_in[5];
    const float* Wproj     = (const float*)d_in[6];
    float* out = (float*)d_out;

    __half *ph, *pl, *xh, *wqth, *wqtl, *wkth, *wktl, *wvth, *wvtl,
           *wph, *wpl, *gth, *hth, *qh, *uth, *aph;
    int *idx, *cnt, *cntp;
    cudaGetSymbolAddress((void**)&ph,   s_ph);   cudaGetSymbolAddress((void**)&pl,   s_pl);
    cudaGetSymbolAddress((void**)&xh,   s_xh);
    cudaGetSymbolAddress((void**)&wqth, s_wqth); cudaGetSymbolAddress((void**)&wqtl, s_wqtl);
    cudaGetSymbolAddress((void**)&wkth, s_wkth); cudaGetSymbolAddress((void**)&wktl, s_wktl);
    cudaGetSymbolAddress((void**)&wvth, s_wvth); cudaGetSymbolAddress((void**)&wvtl, s_wvtl);
    cudaGetSymbolAddress((void**)&wph,  s_wph);  cudaGetSymbolAddress((void**)&wpl,  s_wpl);
    cudaGetSymbolAddress((void**)&gth,  s_gth);
    cudaGetSymbolAddress((void**)&hth,  s_hth);
    cudaGetSymbolAddress((void**)&qh,   s_qh);
    cudaGetSymbolAddress((void**)&uth,  s_uth);
    cudaGetSymbolAddress((void**)&aph,  s_aph);
    cudaGetSymbolAddress((void**)&idx,  g_idx);
    cudaGetSymbolAddress((void**)&cnt,  g_cnt);
    cudaGetSymbolAddress((void**)&cntp, g_cntp);

    cudaFuncSetAttribute(gemm_h<true,false>,
                         cudaFuncAttributeMaxDynamicSharedMemorySize, GEMM_SMEM);
    cudaFuncSetAttribute(gemm_h<false,false>,
                         cudaFuncAttributeMaxDynamicSharedMemorySize, GEMM_SMEM);
    cudaFuncSetAttribute(fold2_kernel,
                         cudaFuncAttributeMaxDynamicSharedMemorySize, GEMM_SMEM);

    const float scale = 0.04419417382415922f;  // 1/sqrt(512)
    dim3 blk(128);

    // mask scan + gather of kept q_x rows (single fp16)
    mask_scan_kernel<<<BATCH, 1024>>>(mask, idx, cnt, cntp);
    gather_h_kernel<<<dim3(NKV, BATCH), 128>>>(q_x, idx, cnt, cntp, xh);

    // splits: prototype, Wproj (plain); Wq, Wk, Wv (transposed)
    split_kernel<<<(BATCH*NQ*DIM/4 + 255)/256, 256>>>(prototype, ph, pl, BATCH*NQ*DIM/4);
    split_kernel<<<(DIM*DIM/4 + 255)/256, 256>>>(Wproj, wph, wpl, DIM*DIM/4);
    transpose_split3_kernel<<<dim3(16, 16, 3), dim3(32, 32)>>>(
        Wq, Wk, Wv, wqth, wqtl, wkth, wktl, wvth, wvtl);

    // both weight folds in one launch:
    //  z=0: Gt = Wk^T(split) @ Wq^T(split)^T ; z=1: Ht = Wproj(split) @ Wv^T(split)^T
    fold2_kernel<<<dim3(DIM/128, DIM/128, 2), blk, GEMM_SMEM>>>(
        wkth, wktl, wqth, wqtl, gth,
        wph,  wpl,  wvth, wvtl, hth);

    // q'[n,d'] = proto(split) @ Gt(single)^T : 2-MMA -> single fp16
    gemm_h<true,false><<<dim3(DIM/128, (BATCH*NQ)/128, 1), blk, GEMM_SMEM>>>(
        ph, pl, gth, nullptr, nullptr, qh, nullptr,
        BATCH*NQ, DIM, DIM, DIM, DIM, 0, 0, 0, 1.0f,
        nullptr, nullptr, nullptr);

    // logits[b] = scale * q'(single) @ xc(single)^T : 1-MMA -> fp16 (in aph)
    gemm_h<false,false><<<dim3(NKV/128, NQ/128, BATCH), blk, GEMM_SMEM>>>(
        qh, nullptr, xh, nullptr, nullptr, aph, nullptr,
        NQ, NKV, DIM, DIM, DIM,
        (size_t)NQ*DIM, (size_t)NKV*DIM, (size_t)NQ*NKV, scale,
        nullptr, cntp, nullptr);

    // softmax in place on fp16 logits -> fp16 probs
    softmax_h_kernel<<<BATCH*NQ, 256>>>(aph, cnt, cntp);

    // uT[b][g,m] = Ht(single) @ xc(single)^T : 1-MMA -> single fp16
    gemm_h<false,false><<<dim3(NKV/128, DIM/128, BATCH), blk, GEMM_SMEM>>>(
        hth, nullptr, xh, nullptr, nullptr, uth, nullptr,
        DIM, NKV, DIM, DIM, DIM,
        0, (size_t)NKV*DIM, (size_t)DIM*NKV, 1.0f,
        nullptr, cntp, nullptr);

    // out[b][n,g] = P(single) @ uT(single)^T : 1-MMA -> fp32
    gemm_h<false,false><<<dim3(DIM/128, NQ/128, BATCH), blk, GEMM_SMEM>>>(
        aph, nullptr, uth, nullptr, out, nullptr, nullptr,
        NQ, DIM, NKV, NKV, NKV,
        (size_t)NQ*NKV, (size_t)DIM*NKV, (size_t)NQ*DIM, 1.0f,
        nullptr, nullptr, cntp);
}

// round 16
// speedup vs baseline: 2.6344x; 1.0301x over previous
#include <cuda_runtime.h>
#include <cuda_fp16.h>
#include <cstdint>
#include <math.h>

#define BATCH 8
#define NQ    1024
#define NKV   4096
#define DIM   512

// ---------------- scratch (device globals: allocation-free) ----------------
__device__ __align__(16) __half s_ph [BATCH*NQ*DIM],  s_pl [BATCH*NQ*DIM];   // prototype split
__device__ __align__(16) __half s_xh [BATCH*NKV*DIM];                        // compacted q_x single
__device__ __align__(16) __half s_wqth[DIM*DIM], s_wqtl[DIM*DIM];            // Wq^T split
__device__ __align__(16) __half s_wkth[DIM*DIM], s_wktl[DIM*DIM];            // Wk^T split
__device__ __align__(16) __half s_wvth[DIM*DIM], s_wvtl[DIM*DIM];            // Wv^T split
__device__ __align__(16) __half s_wph [DIM*DIM], s_wpl [DIM*DIM];            // Wproj split
__device__ __align__(16) __half s_gth [DIM*DIM];                             // Gt single
__device__ __align__(16) __half s_hth [DIM*DIM];                             // Ht single
__device__ __align__(16) __half s_qh [BATCH*NQ*DIM];                         // q' single
__device__ __align__(16) __half s_uth[BATCH*DIM*NKV];                        // uT single
__device__ __align__(16) __half s_aph[(size_t)BATCH*NQ*NKV];                 // logits->probs fp16
__device__ int g_idx[BATCH*NKV];
__device__ int g_cnt[BATCH];
__device__ int g_cntp[BATCH];

// ============================================================================
// helpers
// ============================================================================
__device__ __forceinline__ uint32_t smem_u32(const void* p) {
    uint32_t a;
    asm("{ .reg .u64 t; cvta.to.shared.u64 t, %1; cvt.u32.u64 %0, t; }"
        : "=r"(a) : "l"(p));
    return a;
}
__device__ __forceinline__ void cp_async16(uint32_t saddr, const void* gaddr) {
    asm volatile("cp.async.ca.shared.global [%0], [%1], 16;"
                 :: "r"(saddr), "l"(gaddr) : "memory");
}
__device__ __forceinline__ void cp_commit() {
    asm volatile("cp.async.commit_group;" ::: "memory");
}
__device__ __forceinline__ void cp_wait1() {
    asm volatile("cp.async.wait_group 1;" ::: "memory");
}
__device__ __forceinline__ void cp_wait0() {
    asm volatile("cp.async.wait_group 0;" ::: "memory");
}

// mma.sync m16n8k16 fp16: d += a*b (f32 accumulators in-place)
__device__ __forceinline__ void mma_f16(float* d, const uint32_t* a, const uint32_t* b) {
    asm volatile(
        "mma.sync.aligned.m16n8k16.row.col.f32.f16.f16.f32 "
        "{%0,%1,%2,%3}, {%4,%5,%6,%7}, {%8,%9}, {%0,%1,%2,%3};"
        : "+f"(d[0]), "+f"(d[1]), "+f"(d[2]), "+f"(d[3])
        : "r"(a[0]), "r"(a[1]), "r"(a[2]), "r"(a[3]), "r"(b[0]), "r"(b[1]));
}

__device__ __forceinline__ void ldsm_x4(uint32_t& r0, uint32_t& r1,
                                        uint32_t& r2, uint32_t& r3, uint32_t addr) {
    asm volatile("ldmatrix.sync.aligned.m8n8.x4.shared.b16 {%0,%1,%2,%3}, [%4];"
                 : "=r"(r0), "=r"(r1), "=r"(r2), "=r"(r3) : "r"(addr));
}

// split (x,y) -> packed f16x2 hi + packed f16x2 lo residuals
__device__ __forceinline__ void pack_split(float x, float y, uint32_t& h, uint32_t& l) {
    __half2 hh = __float22half2_rn(make_float2(x, y));
    float2 hf = __half22float2(hh);
    __half2 ll = __float22half2_rn(make_float2(x - hf.x, y - hf.y));
    h = *reinterpret_cast<uint32_t*>(&hh);
    l = *reinterpret_cast<uint32_t*>(&ll);
}
__device__ __forceinline__ uint32_t pack_h(float x, float y) {
    __half2 hh = __float22half2_rn(make_float2(x, y));
    return *reinterpret_cast<uint32_t*>(&hh);
}

// ============================================================================
// mask scan: per batch, build compact index list of kept positions
// ============================================================================
__global__ void __launch_bounds__(1024) mask_scan_kernel(
    const int* __restrict__ mask, int* __restrict__ idx,
    int* __restrict__ cnt, int* __restrict__ cntp)
{
    const int b = blockIdx.x;
    const int t = threadIdx.x;
    const int* m = mask + b * NKV;
    __shared__ int sums[1024];

    int v[4], s = 0;
    #pragma unroll
    for (int i = 0; i < 4; i++) { v[i] = m[t * 4 + i] ? 1 : 0; s += v[i]; }
    sums[t] = s;
    __syncthreads();

    for (int off = 1; off < 1024; off <<= 1) {
        int x = (t >= off) ? sums[t - off] : 0;
        __syncthreads();
        sums[t] += x;
        __syncthreads();
    }

    int o = sums[t] - s;
    #pragma unroll
    for (int i = 0; i < 4; i++)
        if (v[i]) idx[b * NKV + o++] = t * 4 + i;

    if (t == 1023) {
        cnt[b]  = sums[1023];
        cntp[b] = (sums[1023] + 127) & ~127;
    }
}

// ============================================================================
// gather kept q_x rows (by idx) as single fp16; zero the pad rows.
// ============================================================================
__global__ void __launch_bounds__(128) gather_h_kernel(
    const float* __restrict__ qx, const int* __restrict__ idx,
    const int* __restrict__ cnt, const int* __restrict__ cntp,
    __half* __restrict__ xh)
{
    const int b = blockIdx.y;
    const int j = blockIdx.x;
    if (j >= cntp[b]) return;

    const size_t drow = ((size_t)b * NKV + j) * DIM;
    uint2* dh = (uint2*)(xh + drow) + threadIdx.x;

    if (j < cnt[b]) {
        const int r = idx[b * NKV + j];
        float4 vv = *((const float4*)(qx + ((size_t)b * NKV + r) * DIM) + threadIdx.x);
        *dh = make_uint2(pack_h(vv.x, vv.y), pack_h(vv.z, vv.w));
    } else {
        *dh = make_uint2(0u, 0u);
    }
}

// ============================================================================
// elementwise fp32 -> (hi, lo) fp16 split for TWO arrays in one launch
// blocks [0, n4a/256) -> A ; remaining -> B
// ============================================================================
__global__ void __launch_bounds__(256) split2_kernel(
    const float* __restrict__ inA, __half* __restrict__ hA, __half* __restrict__ lA, int n4a,
    const float* __restrict__ inB, __half* __restrict__ hB, __half* __restrict__ lB, int n4b)
{
    int i = blockIdx.x * 256 + threadIdx.x;
    const float* in; __half *h, *l;
    if (i < n4a) { in = inA; h = hA; l = lA; }
    else         { i -= n4a; if (i >= n4b) return; in = inB; h = hB; l = lB; }
    float4 v = ((const float4*)in)[i];
    uint32_t h0, l0, h1, l1;
    pack_split(v.x, v.y, h0, l0);
    pack_split(v.z, v.w, h1, l1);
    ((uint2*)h)[i] = make_uint2(h0, h1);
    ((uint2*)l)[i] = make_uint2(l0, l1);
}

// ============================================================================
// transpose + split for 3 weight matrices: out[d,e] = in[e,d], fp16 hi/lo
// ============================================================================
__global__ void __launch_bounds__(1024) transpose_split3_kernel(
    const float* __restrict__ w0, const float* __restrict__ w1,
    const float* __restrict__ w2,
    __half* __restrict__ h0, __half* __restrict__ l0,
    __half* __restrict__ h1, __half* __restrict__ l1,
    __half* __restrict__ h2, __half* __restrict__ l2)
{
    __shared__ float tile[32][33];
    const int z = blockIdx.z;
    const float* in = z == 0 ? w0 : (z == 1 ? w1 : w2);
    __half* ho = z == 0 ? h0 : (z == 1 ? h1 : h2);
    __half* lo = z == 0 ? l0 : (z == 1 ? l1 : l2);

    int x = blockIdx.x * 32 + threadIdx.x;
    int y = blockIdx.y * 32 + threadIdx.y;
    tile[threadIdx.y][threadIdx.x] = in[y * DIM + x];
    __syncthreads();

    int ox = blockIdx.y * 32 + threadIdx.x;
    int oy = blockIdx.x * 32 + threadIdx.y;
    float v = tile[threadIdx.x][threadIdx.y];
    __half hb = __float2half_rn(v);
    float r = v - __half2float(hb);
    ho[oy * DIM + ox] = hb;
    lo[oy * DIM + ox] = __float2half_rn(r);
}

// ============================================================================
// fp16 split GEMM core (round-9 engine): 128 threads (4 warps, 2x2),
// warp tile 64x64, ldmatrix, 2-stage cp.async, 80B padded rows.
//   C = alpha * (Ah [+Al]) @ (Bh [+Bl])^T ; MMAs: ah*bh [+al*bh if AS] [+ah*bl if BS]
// Pointers are pre-offset for batch; N is the output leading dim.
// Output: fp32 (Cf) | fp16 split (Ch,Cl) | fp16 single (Ch).
// ============================================================================
#define PAD2      40
#define ROW_B     (PAD2 * 2)               // 80 bytes per row
#define TILE_B    (128 * ROW_B)            // 10240
#define STAGE_B   (4 * TILE_B)             // 40960
#define GEMM_SMEM (2 * STAGE_B)            // 81920

template<bool AS, bool BS>
__device__ __forceinline__ void gemm_core(
    const __half* __restrict__ Ah, const __half* __restrict__ Al,
    const __half* __restrict__ Bh, const __half* __restrict__ Bl,
    float* __restrict__ Cf, __half* __restrict__ Ch, __half* __restrict__ Cl,
    int N, int K, int ldA, int ldB, float alpha,
    uint32_t sbase, int m0, int n0)
{
    const int t    = threadIdx.x;
    const int wid  = t >> 5;
    const int lane = t & 31;
    const int g    = lane >> 2;
    const int c    = lane & 3;
    const int warp_m = wid >> 1;    // 0..1
    const int warp_n = wid & 1;     // 0..1

    const uint32_t a_row = lane & 15;
    const uint32_t a_kh  = (lane >> 4) * 16;
    const uint32_t b_row = (lane & 7) + ((lane >> 4) << 3);
    const uint32_t b_kh  = ((lane >> 3) & 1) * 16;

    auto load_tile = [&](int kt, int s) {
        const uint32_t st = sbase + (uint32_t)(s * STAGE_B);
        const int kb = kt * 32;
        #pragma unroll
        for (int ph = 0; ph < 4; ph++) {
            int idx = ph * 128 + t;
            int row = idx >> 2;
            int c4  = idx & 3;
            uint32_t so = (uint32_t)(row * ROW_B + c4 * 16);
            const size_t ga = (size_t)(m0 + row) * ldA + kb + c4 * 8;
            const size_t gb = (size_t)(n0 + row) * ldB + kb + c4 * 8;
            cp_async16(st + 0 * TILE_B + so, Ah + ga);
            if (AS) cp_async16(st + 1 * TILE_B + so, Al + ga);
            cp_async16(st + 2 * TILE_B + so, Bh + gb);
            if (BS) cp_async16(st + 3 * TILE_B + so, Bl + gb);
        }
        cp_commit();
    };

    float acc[4][8][4] = {};

    const int nkt = K >> 5;
    load_tile(0, 0);

    for (int kt = 0; kt < nkt; kt++) {
        const int s = kt & 1;
        if (kt + 1 < nkt) {
            load_tile(kt + 1, s ^ 1);
            cp_wait1();
        } else {
            cp_wait0();
        }
        __syncthreads();

        const uint32_t aB = sbase + s * STAGE_B + warp_m * 64 * ROW_B;
        const uint32_t bB = sbase + s * STAGE_B + 2 * TILE_B + warp_n * 64 * ROW_B;

        #pragma unroll
        for (int ks2 = 0; ks2 < 2; ks2++) {
            const uint32_t kso = ks2 * 32;

            uint32_t bh[8][2], bl[8][2];
            #pragma unroll
            for (int p = 0; p < 4; p++) {
                uint32_t addr = bB + (p * 16 + b_row) * ROW_B + kso + b_kh;
                ldsm_x4(bh[2*p][0], bh[2*p][1], bh[2*p+1][0], bh[2*p+1][1], addr);
                if (BS)
                    ldsm_x4(bl[2*p][0], bl[2*p][1], bl[2*p+1][0], bl[2*p+1][1],
                            addr + TILE_B);
            }

            #pragma unroll
            for (int mt = 0; mt < 4; mt++) {
                uint32_t addr = aB + (mt * 16 + a_row) * ROW_B + kso + a_kh;
                uint32_t ah[4], al[4];
                ldsm_x4(ah[0], ah[1], ah[2], ah[3], addr);
                if (AS)
                    ldsm_x4(al[0], al[1], al[2], al[3], addr + TILE_B);
                #pragma unroll
                for (int nt = 0; nt < 8; nt++) {
                    if (AS) mma_f16(acc[mt][nt], al, bh[nt]);   // small terms first
                    if (BS) mma_f16(acc[mt][nt], ah, bl[nt]);
                    mma_f16(acc[mt][nt], ah, bh[nt]);
                }
            }
        }
        __syncthreads();
    }

    if (Cf) {
        #pragma unroll
        for (int mt = 0; mt < 4; mt++) {
            const int row = m0 + warp_m * 64 + mt * 16 + g;
            #pragma unroll
            for (int nt = 0; nt < 8; nt++) {
                const int col = n0 + warp_n * 64 + nt * 8 + 2 * c;
                *(float2*)(Cf + (size_t)row * N + col) =
                    make_float2(acc[mt][nt][0] * alpha, acc[mt][nt][1] * alpha);
                *(float2*)(Cf + (size_t)(row + 8) * N + col) =
                    make_float2(acc[mt][nt][2] * alpha, acc[mt][nt][3] * alpha);
            }
        }
    } else if (Cl) {
        #pragma unroll
        for (int mt = 0; mt < 4; mt++) {
            const int row = m0 + warp_m * 64 + mt * 16 + g;
            #pragma unroll
            for (int nt = 0; nt < 8; nt++) {
                const int col = n0 + warp_n * 64 + nt * 8 + 2 * c;
                uint32_t h, l;
                pack_split(acc[mt][nt][0] * alpha, acc[mt][nt][1] * alpha, h, l);
                *(uint32_t*)(Ch + (size_t)row * N + col) = h;
                *(uint32_t*)(Cl + (size_t)row * N + col) = l;
                pack_split(acc[mt][nt][2] * alpha, acc[mt][nt][3] * alpha, h, l);
                *(uint32_t*)(Ch + (size_t)(row + 8) * N + col) = h;
                *(uint32_t*)(Cl + (size_t)(row + 8) * N + col) = l;
            }
        }
    } else {
        #pragma unroll
        for (int mt = 0; mt < 4; mt++) {
            const int row = m0 + warp_m * 64 + mt * 16 + g;
            #pragma unroll
            for (int nt = 0; nt < 8; nt++) {
                const int col = n0 + warp_n * 64 + nt * 8 + 2 * c;
                *(uint32_t*)(Ch + (size_t)row * N + col) =
                    pack_h(acc[mt][nt][0] * alpha, acc[mt][nt][1] * alpha);
                *(uint32_t*)(Ch + (size_t)(row + 8) * N + col) =
                    pack_h(acc[mt][nt][2] * alpha, acc[mt][nt][3] * alpha);
            }
        }
    }
}

template<bool AS, bool BS>
__global__ void __launch_bounds__(128, 2) gemm_h(
    const __half* __restrict__ Ah, const __half* __restrict__ Al,
    const __half* __restrict__ Bh, const __half* __restrict__ Bl,
    float* __restrict__ Cf,
    __half* __restrict__ Ch, __half* __restrict__ Cl,
    int M, int N, int K, int ldA, int ldB,
    size_t sA, size_t sB, size_t sC, float alpha,
    const int* __restrict__ mlim, const int* __restrict__ nlim,
    const int* __restrict__ kdyn)
{
    extern __shared__ __align__(16) char smem[];
    const uint32_t sbase = smem_u32(smem);

    const int m0 = blockIdx.y * 128;
    const int n0 = blockIdx.x * 128;
    if (mlim && m0 >= mlim[blockIdx.z]) return;
    if (nlim && n0 >= nlim[blockIdx.z]) return;
    if (kdyn) K = kdyn[blockIdx.z];

    Ah += (size_t)blockIdx.z * sA;
    Bh += (size_t)blockIdx.z * sB;
    if (AS) Al += (size_t)blockIdx.z * sA;
    if (BS) Bl += (size_t)blockIdx.z * sB;
    if (Cf) Cf += (size_t)blockIdx.z * sC;
    if (Ch) Ch += (size_t)blockIdx.z * sC;
    if (Cl) Cl += (size_t)blockIdx.z * sC;

    gemm_core<AS, BS>(Ah, Al, Bh, Bl, Cf, Ch, Cl,
                      N, K, ldA, ldB, alpha, sbase, m0, n0);
}

// both 512x512x512 weight folds in ONE launch: blockIdx.z selects the fold
__global__ void __launch_bounds__(128, 2) fold2_kernel(
    const __half* __restrict__ a0h, const __half* __restrict__ a0l,
    const __half* __restrict__ b0h, const __half* __restrict__ b0l,
    __half* __restrict__ c0,
    const __half* __restrict__ a1h, const __half* __restrict__ a1l,
    const __half* __restrict__ b1h, const __half* __restrict__ b1l,
    __half* __restrict__ c1)
{
    extern __shared__ __align__(16) char smem[];
    const uint32_t sbase = smem_u32(smem);
    const int m0 = blockIdx.y * 128;
    const int n0 = blockIdx.x * 128;
    const bool z = blockIdx.z != 0;
    gemm_core<true, true>(z ? a1h : a0h, z ? a1l : a0l,
                          z ? b1h : b0h, z ? b1l : b0l,
                          nullptr, z ? c1 : c0, nullptr,
                          DIM, DIM, DIM, DIM, 1.0f, sbase, m0, n0);
}

// ============================================================================
// merged q' + uT launch (independent GEMMs, 1-D grid decode):
//   CTA 0..255    : q'[n,d'] = proto(split) @ Gt(single)^T  (M=8192,N=512,K=512)
//   CTA 256..1279 : uT[b][g,m] = Ht(single) @ xc[b](single)^T (per batch,
//                   M=512, N=cntp[b] culled, K=512)
// ============================================================================
__global__ void __launch_bounds__(128, 2) qu_kernel(
    const __half* __restrict__ ph, const __half* __restrict__ pl,
    const __half* __restrict__ gth, __half* __restrict__ qh,
    const __half* __restrict__ hth, const __half* __restrict__ xh,
    __half* __restrict__ uth, const int* __restrict__ cntp)
{
    extern __shared__ __align__(16) char smem[];
    const uint32_t sbase = smem_u32(smem);
    const int i = blockIdx.x;

    if (i < 256) {
        const int m0 = (i >> 2) * 128;      // 64 m-tiles of 8192
        const int n0 = (i & 3) * 128;       // 4 n-tiles of 512
        gemm_core<true, false>(ph, pl, gth, nullptr, nullptr, qh, nullptr,
                               DIM, DIM, DIM, DIM, 1.0f, sbase, m0, n0);
    } else {
        const int j  = i - 256;
        const int b  = j >> 7;              // 8 batches x 128 tiles
        const int r  = j & 127;
        const int n0 = (r & 31) * 128;      // 32 kv-tiles
        const int m0 = (r >> 5) * 128;      // 4 dim-tiles
        if (n0 >= cntp[b]) return;
        gemm_core<false, false>(hth, nullptr, xh + (size_t)b * NKV * DIM, nullptr,
                                nullptr, uth + (size_t)b * (size_t)DIM * NKV, nullptr,
                                NKV, DIM, DIM, DIM, 1.0f, sbase, m0, n0);
    }
}

// ============================================================================
// softmax in place on fp16 logits -> fp16 probs; row width cnt[b], pad to cntp.
// ============================================================================
__global__ void __launch_bounds__(256) softmax_h_kernel(
    __half* __restrict__ P, const int* __restrict__ cnt,
    const int* __restrict__ cntp)
{
    const int row = blockIdx.x;
    const int b   = row >> 10;             // NQ = 1024
    const int cn  = cnt[b];
    const int cp  = cntp[b];
    uint32_t* p = (uint32_t*)(P + (size_t)row * NKV);

    float2 v[8];
    float mx = -3.0e38f;
    #pragma unroll
    for (int i = 0; i < 8; i++) {
        int j2 = threadIdx.x + i * 256;
        int j  = 2 * j2;
        float2 x = make_float2(-3.0e38f, -3.0e38f);
        if (j < cp) {
            uint32_t w = p[j2];
            __half2 hv = *reinterpret_cast<__half2*>(&w);
            x = __half22float2(hv);
            if (j     >= cn) x.x = -3.0e38f;
            if (j + 1 >= cn) x.y = -3.0e38f;
        }
        v[i] = x;
        mx = fmaxf(mx, fmaxf(x.x, x.y));
    }

    __shared__ float red[8];
    #pragma unroll
    for (int o = 16; o; o >>= 1) mx = fmaxf(mx, __shfl_xor_sync(0xffffffffu, mx, o));
    if ((threadIdx.x & 31) == 0) red[threadIdx.x >> 5] = mx;
    __syncthreads();
    float bm = red[0];
    #pragma unroll
    for (int w = 1; w < 8; w++) bm = fmaxf(bm, red[w]);
    __syncthreads();

    float sum = 0.0f;
    #pragma unroll
    for (int i = 0; i < 8; i++) {
        v[i].x = __expf(v[i].x - bm);
        v[i].y = __expf(v[i].y - bm);
        sum += v[i].x + v[i].y;
    }
    #pragma unroll
    for (int o = 16; o; o >>= 1) sum += __shfl_xor_sync(0xffffffffu, sum, o);
    if ((threadIdx.x & 31) == 0) red[threadIdx.x >> 5] = sum;
    __syncthreads();
    float ts = red[0];
    #pragma unroll
    for (int w = 1; w < 8; w++) ts += red[w];
    float inv = 1.0f / ts;

    #pragma unroll
    for (int i = 0; i < 8; i++) {
        int j2 = threadIdx.x + i * 256;
        int j  = 2 * j2;
        if (j < cp)
            p[j2] = pack_h(v[i].x * inv, v[i].y * inv);
    }
}

// ============================================================================
// launch
// ============================================================================
extern "C" void kernel_launch(void* const* d_in, const int* in_sizes, int n_in,
                              void* d_out, int out_size)
{
    const float* prototype = (const float*)d_in[0];
    const float* q_x       = (const float*)d_in[1];
    const int*   mask      = (const int*)  d_in[2];
    const float* Wq        = (const float*)d_in[3];
    const float* Wk        = (const float*)d_in[4];
    const float* Wv        = (const float*)d_in[5];
    const float* Wproj     = (const float*)d_in[6];
    float* out = (float*)d_out;

    __half *ph, *pl, *xh, *wqth, *wqtl, *wkth, *wktl, *wvth, *wvtl,
           *wph, *wpl, *gth, *hth, *qh, *uth, *aph;
    int *idx, *cnt, *cntp;
    cudaGetSymbolAddress((void**)&ph,   s_ph);   cudaGetSymbolAddress((void**)&pl,   s_pl);
    cudaGetSymbolAddress((void**)&xh,   s_xh);
    cudaGetSymbolAddress((void**)&wqth, s_wqth); cudaGetSymbolAddress((void**)&wqtl, s_wqtl);
    cudaGetSymbolAddress((void**)&wkth, s_wkth); cudaGetSymbolAddress((void**)&wktl, s_wktl);
    cudaGetSymbolAddress((void**)&wvth, s_wvth); cudaGetSymbolAddress((void**)&wvtl, s_wvtl);
    cudaGetSymbolAddress((void**)&wph,  s_wph);  cudaGetSymbolAddress((void**)&wpl,  s_wpl);
    cudaGetSymbolAddress((void**)&gth,  s_gth);
    cudaGetSymbolAddress((void**)&hth,  s_hth);
    cudaGetSymbolAddress((void**)&qh,   s_qh);
    cudaGetSymbolAddress((void**)&uth,  s_uth);
    cudaGetSymbolAddress((void**)&aph,  s_aph);
    cudaGetSymbolAddress((void**)&idx,  g_idx);
    cudaGetSymbolAddress((void**)&cnt,  g_cnt);
    cudaGetSymbolAddress((void**)&cntp, g_cntp);

    cudaFuncSetAttribute(gemm_h<false,false>,
                         cudaFuncAttributeMaxDynamicSharedMemorySize, GEMM_SMEM);
    cudaFuncSetAttribute(fold2_kernel,
                         cudaFuncAttributeMaxDynamicSharedMemorySize, GEMM_SMEM);
    cudaFuncSetAttribute(qu_kernel,
                         cudaFuncAttributeMaxDynamicSharedMemorySize, GEMM_SMEM);

    const float scale = 0.04419417382415922f;  // 1/sqrt(512)
    dim3 blk(128);

    // mask scan + gather of kept q_x rows (single fp16)
    mask_scan_kernel<<<BATCH, 1024>>>(mask, idx, cnt, cntp);
    gather_h_kernel<<<dim3(NKV, BATCH), 128>>>(q_x, idx, cnt, cntp, xh);

    // splits: prototype + Wproj in one launch; Wq/Wk/Wv transposed
    {
        const int n4a = BATCH * NQ * DIM / 4;
        const int n4b = DIM * DIM / 4;
        split2_kernel<<<(n4a + n4b + 255) / 256, 256>>>(
            prototype, ph, pl, n4a, Wproj, wph, wpl, n4b);
    }
    transpose_split3_kernel<<<dim3(16, 16, 3), dim3(32, 32)>>>(
        Wq, Wk, Wv, wqth, wqtl, wkth, wktl, wvth, wvtl);

    // both weight folds in one launch:
    //  z=0: Gt = Wk^T(split) @ Wq^T(split)^T ; z=1: Ht = Wproj(split) @ Wv^T(split)^T
    fold2_kernel<<<dim3(DIM/128, DIM/128, 2), blk, GEMM_SMEM>>>(
        wkth, wktl, wqth, wqtl, gth,
        wph,  wpl,  wvth, wvtl, hth);

    // merged: q' (proto.Gt^T) and uT (Ht.xc^T) in one 1280-CTA launch
    qu_kernel<<<1280, blk, GEMM_SMEM>>>(ph, pl, gth, qh, hth, xh, uth, cntp);

    // logits[b] = scale * q'(single) @ xc(single)^T : 1-MMA -> fp16 (in aph)
    gemm_h<false,false><<<dim3(NKV/128, NQ/128, BATCH), blk, GEMM_SMEM>>>(
        qh, nullptr, xh, nullptr, nullptr, aph, nullptr,
        NQ, NKV, DIM, DIM, DIM,
        (size_t)NQ*DIM, (size_t)NKV*DIM, (size_t)NQ*NKV, scale,
        nullptr, cntp, nullptr);

    // softmax in place on fp16 logits -> fp16 probs
    softmax_h_kernel<<<BATCH*NQ, 256>>>(aph, cnt, cntp);

    // out[b][n,g] = P(single) @ uT(single)^T : 1-MMA -> fp32
    gemm_h<false,false><<<dim3(DIM/128, NQ/128, BATCH), blk, GEMM_SMEM>>>(
        aph, nullptr, uth, nullptr, out, nullptr, nullptr,
        NQ, DIM, NKV, NKV, NKV,
        (size_t)NQ*NKV, (size_t)DIM*NKV, (size_t)NQ*DIM, 1.0f,
        nullptr, nullptr, cntp);
}

// round 17
// speedup vs baseline: 2.6785x; 1.0167x over previous
#include <cuda_runtime.h>
#include <cuda_fp16.h>
#include <cstdint>
#include <math.h>

#define BATCH 8
#define NQ    1024
#define NKV   4096
#define DIM   512

// ---------------- scratch (device globals: allocation-free) ----------------
__device__ __align__(16) __half s_ph [BATCH*NQ*DIM],  s_pl [BATCH*NQ*DIM];   // prototype split
__device__ __align__(16) __half s_xh [BATCH*NKV*DIM];                        // compacted q_x single
__device__ __align__(16) __half s_wqth[DIM*DIM], s_wqtl[DIM*DIM];            // Wq^T split
__device__ __align__(16) __half s_wkth[DIM*DIM], s_wktl[DIM*DIM];            // Wk^T split
__device__ __align__(16) __half s_wvth[DIM*DIM], s_wvtl[DIM*DIM];            // Wv^T split
__device__ __align__(16) __half s_wph [DIM*DIM], s_wpl [DIM*DIM];            // Wproj split
__device__ __align__(16) __half s_gth [DIM*DIM];                             // Gt single
__device__ __align__(16) __half s_hth [DIM*DIM];                             // Ht single
__device__ __align__(16) __half s_qh [BATCH*NQ*DIM];                         // q' single
__device__ __align__(16) __half s_uth[BATCH*DIM*NKV];                        // uT single
__device__ __align__(16) __half s_aph[(size_t)BATCH*NQ*NKV];                 // logits->probs fp16
__device__ int g_idx[BATCH*NKV];
__device__ int g_cnt[BATCH];
__device__ int g_cntp[BATCH];

// ============================================================================
// helpers
// ============================================================================
__device__ __forceinline__ uint32_t smem_u32(const void* p) {
    uint32_t a;
    asm("{ .reg .u64 t; cvta.to.shared.u64 t, %1; cvt.u32.u64 %0, t; }"
        : "=r"(a) : "l"(p));
    return a;
}
__device__ __forceinline__ void cp_async16(uint32_t saddr, const void* gaddr) {
    asm volatile("cp.async.ca.shared.global [%0], [%1], 16;"
                 :: "r"(saddr), "l"(gaddr) : "memory");
}
__device__ __forceinline__ void cp_commit() {
    asm volatile("cp.async.commit_group;" ::: "memory");
}
template<int N>
__device__ __forceinline__ void cp_wait() {
    asm volatile("cp.async.wait_group %0;" :: "n"(N) : "memory");
}

// mma.sync m16n8k16 fp16: d += a*b (f32 accumulators in-place)
__device__ __forceinline__ void mma_f16(float* d, const uint32_t* a, const uint32_t* b) {
    asm volatile(
        "mma.sync.aligned.m16n8k16.row.col.f32.f16.f16.f32 "
        "{%0,%1,%2,%3}, {%4,%5,%6,%7}, {%8,%9}, {%0,%1,%2,%3};"
        : "+f"(d[0]), "+f"(d[1]), "+f"(d[2]), "+f"(d[3])
        : "r"(a[0]), "r"(a[1]), "r"(a[2]), "r"(a[3]), "r"(b[0]), "r"(b[1]));
}

__device__ __forceinline__ void ldsm_x4(uint32_t& r0, uint32_t& r1,
                                        uint32_t& r2, uint32_t& r3, uint32_t addr) {
    asm volatile("ldmatrix.sync.aligned.m8n8.x4.shared.b16 {%0,%1,%2,%3}, [%4];"
                 : "=r"(r0), "=r"(r1), "=r"(r2), "=r"(r3) : "r"(addr));
}

// split (x,y) -> packed f16x2 hi + packed f16x2 lo residuals
__device__ __forceinline__ void pack_split(float x, float y, uint32_t& h, uint32_t& l) {
    __half2 hh = __float22half2_rn(make_float2(x, y));
    float2 hf = __half22float2(hh);
    __half2 ll = __float22half2_rn(make_float2(x - hf.x, y - hf.y));
    h = *reinterpret_cast<uint32_t*>(&hh);
    l = *reinterpret_cast<uint32_t*>(&ll);
}
__device__ __forceinline__ uint32_t pack_h(float x, float y) {
    __half2 hh = __float22half2_rn(make_float2(x, y));
    return *reinterpret_cast<uint32_t*>(&hh);
}

// ============================================================================
// mask scan: per batch, build compact index list of kept positions
// ============================================================================
__global__ void __launch_bounds__(1024) mask_scan_kernel(
    const int* __restrict__ mask, int* __restrict__ idx,
    int* __restrict__ cnt, int* __restrict__ cntp)
{
    const int b = blockIdx.x;
    const int t = threadIdx.x;
    const int* m = mask + b * NKV;
    __shared__ int sums[1024];

    int v[4], s = 0;
    #pragma unroll
    for (int i = 0; i < 4; i++) { v[i] = m[t * 4 + i] ? 1 : 0; s += v[i]; }
    sums[t] = s;
    __syncthreads();

    for (int off = 1; off < 1024; off <<= 1) {
        int x = (t >= off) ? sums[t - off] : 0;
        __syncthreads();
        sums[t] += x;
        __syncthreads();
    }

    int o = sums[t] - s;
    #pragma unroll
    for (int i = 0; i < 4; i++)
        if (v[i]) idx[b * NKV + o++] = t * 4 + i;

    if (t == 1023) {
        cnt[b]  = sums[1023];
        cntp[b] = (sums[1023] + 127) & ~127;
    }
}

// ============================================================================
// gather kept q_x rows (by idx) as single fp16; zero the pad rows.
// ============================================================================
__global__ void __launch_bounds__(128) gather_h_kernel(
    const float* __restrict__ qx, const int* __restrict__ idx,
    const int* __restrict__ cnt, const int* __restrict__ cntp,
    __half* __restrict__ xh)
{
    const int b = blockIdx.y;
    const int j = blockIdx.x;
    if (j >= cntp[b]) return;

    const size_t drow = ((size_t)b * NKV + j) * DIM;
    uint2* dh = (uint2*)(xh + drow) + threadIdx.x;

    if (j < cnt[b]) {
        const int r = idx[b * NKV + j];
        float4 vv = *((const float4*)(qx + ((size_t)b * NKV + r) * DIM) + threadIdx.x);
        *dh = make_uint2(pack_h(vv.x, vv.y), pack_h(vv.z, vv.w));
    } else {
        *dh = make_uint2(0u, 0u);
    }
}

// ============================================================================
// elementwise fp32 -> (hi, lo) fp16 split for TWO arrays in one launch
// ============================================================================
__global__ void __launch_bounds__(256) split2_kernel(
    const float* __restrict__ inA, __half* __restrict__ hA, __half* __restrict__ lA, int n4a,
    const float* __restrict__ inB, __half* __restrict__ hB, __half* __restrict__ lB, int n4b)
{
    int i = blockIdx.x * 256 + threadIdx.x;
    const float* in; __half *h, *l;
    if (i < n4a) { in = inA; h = hA; l = lA; }
    else         { i -= n4a; if (i >= n4b) return; in = inB; h = hB; l = lB; }
    float4 v = ((const float4*)in)[i];
    uint32_t h0, l0, h1, l1;
    pack_split(v.x, v.y, h0, l0);
    pack_split(v.z, v.w, h1, l1);
    ((uint2*)h)[i] = make_uint2(h0, h1);
    ((uint2*)l)[i] = make_uint2(l0, l1);
}

// ============================================================================
// transpose + split for 3 weight matrices: out[d,e] = in[e,d], fp16 hi/lo
// ============================================================================
__global__ void __launch_bounds__(1024) transpose_split3_kernel(
    const float* __restrict__ w0, const float* __restrict__ w1,
    const float* __restrict__ w2,
    __half* __restrict__ h0, __half* __restrict__ l0,
    __half* __restrict__ h1, __half* __restrict__ l1,
    __half* __restrict__ h2, __half* __restrict__ l2)
{
    __shared__ float tile[32][33];
    const int z = blockIdx.z;
    const float* in = z == 0 ? w0 : (z == 1 ? w1 : w2);
    __half* ho = z == 0 ? h0 : (z == 1 ? h1 : h2);
    __half* lo = z == 0 ? l0 : (z == 1 ? l1 : l2);

    int x = blockIdx.x * 32 + threadIdx.x;
    int y = blockIdx.y * 32 + threadIdx.y;
    tile[threadIdx.y][threadIdx.x] = in[y * DIM + x];
    __syncthreads();

    int ox = blockIdx.y * 32 + threadIdx.x;
    int oy = blockIdx.x * 32 + threadIdx.y;
    float v = tile[threadIdx.x][threadIdx.y];
    __half hb = __float2half_rn(v);
    float r = v - __half2float(hb);
    ho[oy * DIM + ox] = hb;
    lo[oy * DIM + ox] = __float2half_rn(r);
}

// ============================================================================
// fp16 split GEMM core: 128 threads (4 warps, 2x2), warp tile 64x64,
// ldmatrix, NST-stage cp.async, 80B padded rows, COMPACT stage layout:
// only the operand arrays in use are allocated (stage = (2+AS+BS) tiles).
//   C = alpha * (Ah [+Al]) @ (Bh [+Bl])^T
// Output: fp32 (Cf) | fp16 split (Ch,Cl) | fp16 single (Ch).
// ============================================================================
#define PAD2      40
#define ROW_B     (PAD2 * 2)               // 80 bytes per row
#define TILE_B    (128 * ROW_B)            // 10240
#define SMEM_1MMA3 (3 * 2 * TILE_B)        // 61440 (1-MMA, 3 stages)
#define SMEM_AS2   (2 * 3 * TILE_B)        // 61440 (A-split, 2 stages)
#define SMEM_AB2   (2 * 4 * TILE_B)        // 81920 (AB-split, 2 stages)

template<bool AS, bool BS, int NST>
__device__ __forceinline__ void gemm_core(
    const __half* __restrict__ Ah, const __half* __restrict__ Al,
    const __half* __restrict__ Bh, const __half* __restrict__ Bl,
    float* __restrict__ Cf, __half* __restrict__ Ch, __half* __restrict__ Cl,
    int N, int K, int ldA, int ldB, float alpha,
    uint32_t sbase, int m0, int n0)
{
    constexpr int NOPS   = 2 + (AS ? 1 : 0) + (BS ? 1 : 0);
    constexpr uint32_t STAGE = NOPS * TILE_B;
    constexpr uint32_t OFF_AL = TILE_B;                       // valid iff AS
    constexpr uint32_t OFF_B  = (AS ? 2u : 1u) * TILE_B;
    constexpr uint32_t OFF_BL = OFF_B + TILE_B;               // valid iff BS

    const int t    = threadIdx.x;
    const int wid  = t >> 5;
    const int lane = t & 31;
    const int g    = lane >> 2;
    const int c    = lane & 3;
    const int warp_m = wid >> 1;    // 0..1
    const int warp_n = wid & 1;     // 0..1

    const uint32_t a_row = lane & 15;
    const uint32_t a_kh  = (lane >> 4) * 16;
    const uint32_t b_row = (lane & 7) + ((lane >> 4) << 3);
    const uint32_t b_kh  = ((lane >> 3) & 1) * 16;

    auto load_tile = [&](int kt, int s) {
        const uint32_t st = sbase + (uint32_t)s * STAGE;
        const int kb = kt * 32;
        #pragma unroll
        for (int ph = 0; ph < 4; ph++) {
            int idx = ph * 128 + t;
            int row = idx >> 2;
            int c4  = idx & 3;
            uint32_t so = (uint32_t)(row * ROW_B + c4 * 16);
            const size_t ga = (size_t)(m0 + row) * ldA + kb + c4 * 8;
            const size_t gb = (size_t)(n0 + row) * ldB + kb + c4 * 8;
            cp_async16(st + so, Ah + ga);
            if (AS) cp_async16(st + OFF_AL + so, Al + ga);
            cp_async16(st + OFF_B + so, Bh + gb);
            if (BS) cp_async16(st + OFF_BL + so, Bl + gb);
        }
        cp_commit();
    };

    float acc[4][8][4] = {};

    const int nkt = K >> 5;
    #pragma unroll
    for (int s = 0; s < NST - 1; s++)
        load_tile(s, s);

    for (int kt = 0; kt < nkt; kt++) {
        const int s = kt % NST;
        if (kt + NST - 1 < nkt)
            load_tile(kt + NST - 1, (kt + NST - 1) % NST);
        const int rem = nkt - 1 - kt;
        if (NST >= 3 && rem >= 2)      cp_wait<2>();
        else if (rem >= 1)             cp_wait<1>();
        else                           cp_wait<0>();
        __syncthreads();

        const uint32_t aB = sbase + s * STAGE + warp_m * 64 * ROW_B;
        const uint32_t bB = sbase + s * STAGE + OFF_B + warp_n * 64 * ROW_B;

        #pragma unroll
        for (int ks2 = 0; ks2 < 2; ks2++) {
            const uint32_t kso = ks2 * 32;

            uint32_t bh[8][2], bl[8][2];
            #pragma unroll
            for (int p = 0; p < 4; p++) {
                uint32_t addr = bB + (p * 16 + b_row) * ROW_B + kso + b_kh;
                ldsm_x4(bh[2*p][0], bh[2*p][1], bh[2*p+1][0], bh[2*p+1][1], addr);
                if (BS)
                    ldsm_x4(bl[2*p][0], bl[2*p][1], bl[2*p+1][0], bl[2*p+1][1],
                            addr + TILE_B);
            }

            #pragma unroll
            for (int mt = 0; mt < 4; mt++) {
                uint32_t addr = aB + (mt * 16 + a_row) * ROW_B + kso + a_kh;
                uint32_t ah[4], al[4];
                ldsm_x4(ah[0], ah[1], ah[2], ah[3], addr);
                if (AS)
                    ldsm_x4(al[0], al[1], al[2], al[3], addr + TILE_B);
                #pragma unroll
                for (int nt = 0; nt < 8; nt++) {
                    if (AS) mma_f16(acc[mt][nt], al, bh[nt]);   // small terms first
                    if (BS) mma_f16(acc[mt][nt], ah, bl[nt]);
                    mma_f16(acc[mt][nt], ah, bh[nt]);
                }
            }
        }
        __syncthreads();
    }

    if (Cf) {
        #pragma unroll
        for (int mt = 0; mt < 4; mt++) {
            const int row = m0 + warp_m * 64 + mt * 16 + g;
            #pragma unroll
            for (int nt = 0; nt < 8; nt++) {
                const int col = n0 + warp_n * 64 + nt * 8 + 2 * c;
                *(float2*)(Cf + (size_t)row * N + col) =
                    make_float2(acc[mt][nt][0] * alpha, acc[mt][nt][1] * alpha);
                *(float2*)(Cf + (size_t)(row + 8) * N + col) =
                    make_float2(acc[mt][nt][2] * alpha, acc[mt][nt][3] * alpha);
            }
        }
    } else if (Cl) {
        #pragma unroll
        for (int mt = 0; mt < 4; mt++) {
            const int row = m0 + warp_m * 64 + mt * 16 + g;
            #pragma unroll
            for (int nt = 0; nt < 8; nt++) {
                const int col = n0 + warp_n * 64 + nt * 8 + 2 * c;
                uint32_t h, l;
                pack_split(acc[mt][nt][0] * alpha, acc[mt][nt][1] * alpha, h, l);
                *(uint32_t*)(Ch + (size_t)row * N + col) = h;
                *(uint32_t*)(Cl + (size_t)row * N + col) = l;
                pack_split(acc[mt][nt][2] * alpha, acc[mt][nt][3] * alpha, h, l);
                *(uint32_t*)(Ch + (size_t)(row + 8) * N + col) = h;
                *(uint32_t*)(Cl + (size_t)(row + 8) * N + col) = l;
            }
        }
    } else {
        #pragma unroll
        for (int mt = 0; mt < 4; mt++) {
            const int row = m0 + warp_m * 64 + mt * 16 + g;
            #pragma unroll
            for (int nt = 0; nt < 8; nt++) {
                const int col = n0 + warp_n * 64 + nt * 8 + 2 * c;
                *(uint32_t*)(Ch + (size_t)row * N + col) =
                    pack_h(acc[mt][nt][0] * alpha, acc[mt][nt][1] * alpha);
                *(uint32_t*)(Ch + (size_t)(row + 8) * N + col) =
                    pack_h(acc[mt][nt][2] * alpha, acc[mt][nt][3] * alpha);
            }
        }
    }
}

// 1-MMA batched GEMM, 3-stage pipeline (QK and PV)
__global__ void __launch_bounds__(128, 2) gemm_1mma(
    const __half* __restrict__ Ah, const __half* __restrict__ Bh,
    float* __restrict__ Cf, __half* __restrict__ Ch,
    int N, int K, int ldA, int ldB,
    size_t sA, size_t sB, size_t sC, float alpha,
    const int* __restrict__ nlim, const int* __restrict__ kdyn)
{
    extern __shared__ __align__(16) char smem[];
    const uint32_t sbase = smem_u32(smem);

    const int m0 = blockIdx.y * 128;
    const int n0 = blockIdx.x * 128;
    if (nlim && n0 >= nlim[blockIdx.z]) return;
    if (kdyn) K = kdyn[blockIdx.z];

    Ah += (size_t)blockIdx.z * sA;
    Bh += (size_t)blockIdx.z * sB;
    if (Cf) Cf += (size_t)blockIdx.z * sC;
    if (Ch) Ch += (size_t)blockIdx.z * sC;

    gemm_core<false, false, 3>(Ah, nullptr, Bh, nullptr, Cf, Ch, nullptr,
                               N, K, ldA, ldB, alpha, sbase, m0, n0);
}

// both 512x512x512 weight folds in ONE launch: blockIdx.z selects the fold
__global__ void __launch_bounds__(128, 2) fold2_kernel(
    const __half* __restrict__ a0h, const __half* __restrict__ a0l,
    const __half* __restrict__ b0h, const __half* __restrict__ b0l,
    __half* __restrict__ c0,
    const __half* __restrict__ a1h, const __half* __restrict__ a1l,
    const __half* __restrict__ b1h, const __half* __restrict__ b1l,
    __half* __restrict__ c1)
{
    extern __shared__ __align__(16) char smem[];
    const uint32_t sbase = smem_u32(smem);
    const int m0 = blockIdx.y * 128;
    const int n0 = blockIdx.x * 128;
    const bool z = blockIdx.z != 0;
    gemm_core<true, true, 2>(z ? a1h : a0h, z ? a1l : a0l,
                             z ? b1h : b0h, z ? b1l : b0l,
                             nullptr, z ? c1 : c0, nullptr,
                             DIM, DIM, DIM, DIM, 1.0f, sbase, m0, n0);
}

// ============================================================================
// merged q' + uT launch (independent GEMMs, 1-D grid decode):
//   CTA 0..255    : q' = proto(split) @ Gt^T      (AS, 2-stage, 61440 B)
//   CTA 256..1279 : uT[b] = Ht @ xc[b]^T          (1-MMA, 3-stage, 61440 B)
// ============================================================================
__global__ void __launch_bounds__(128, 2) qu_kernel(
    const __half* __restrict__ ph, const __half* __restrict__ pl,
    const __half* __restrict__ gth, __half* __restrict__ qh,
    const __half* __restrict__ hth, const __half* __restrict__ xh,
    __half* __restrict__ uth, const int* __restrict__ cntp)
{
    extern __shared__ __align__(16) char smem[];
    const uint32_t sbase = smem_u32(smem);
    const int i = blockIdx.x;

    if (i < 256) {
        const int m0 = (i >> 2) * 128;      // 64 m-tiles of 8192
        const int n0 = (i & 3) * 128;       // 4 n-tiles of 512
        gemm_core<true, false, 2>(ph, pl, gth, nullptr, nullptr, qh, nullptr,
                                  DIM, DIM, DIM, DIM, 1.0f, sbase, m0, n0);
    } else {
        const int j  = i - 256;
        const int b  = j >> 7;              // 8 batches x 128 tiles
        const int r  = j & 127;
        const int n0 = (r & 31) * 128;      // 32 kv-tiles
        const int m0 = (r >> 5) * 128;      // 4 dim-tiles
        if (n0 >= cntp[b]) return;
        gemm_core<false, false, 3>(hth, nullptr, xh + (size_t)b * NKV * DIM, nullptr,
                                   nullptr, uth + (size_t)b * (size_t)DIM * NKV, nullptr,
                                   NKV, DIM, DIM, DIM, 1.0f, sbase, m0, n0);
    }
}

// ============================================================================
// softmax in place on fp16 logits -> fp16 probs; row width cnt[b], pad to cntp.
// ============================================================================
__global__ void __launch_bounds__(256) softmax_h_kernel(
    __half* __restrict__ P, const int* __restrict__ cnt,
    const int* __restrict__ cntp)
{
    const int row = blockIdx.x;
    const int b   = row >> 10;             // NQ = 1024
    const int cn  = cnt[b];
    const int cp  = cntp[b];
    uint32_t* p = (uint32_t*)(P + (size_t)row * NKV);

    float2 v[8];
    float mx = -3.0e38f;
    #pragma unroll
    for (int i = 0; i < 8; i++) {
        int j2 = threadIdx.x + i * 256;
        int j  = 2 * j2;
        float2 x = make_float2(-3.0e38f, -3.0e38f);
        if (j < cp) {
            uint32_t w = p[j2];
            __half2 hv = *reinterpret_cast<__half2*>(&w);
            x = __half22float2(hv);
            if (j     >= cn) x.x = -3.0e38f;
            if (j + 1 >= cn) x.y = -3.0e38f;
        }
        v[i] = x;
        mx = fmaxf(mx, fmaxf(x.x, x.y));
    }

    __shared__ float red[8];
    #pragma unroll
    for (int o = 16; o; o >>= 1) mx = fmaxf(mx, __shfl_xor_sync(0xffffffffu, mx, o));
    if ((threadIdx.x & 31) == 0) red[threadIdx.x >> 5] = mx;
    __syncthreads();
    float bm = red[0];
    #pragma unroll
    for (int w = 1; w < 8; w++) bm = fmaxf(bm, red[w]);
    __syncthreads();

    float sum = 0.0f;
    #pragma unroll
    for (int i = 0; i < 8; i++) {
        v[i].x = __expf(v[i].x - bm);
        v[i].y = __expf(v[i].y - bm);
        sum += v[i].x + v[i].y;
    }
    #pragma unroll
    for (int o = 16; o; o >>= 1) sum += __shfl_xor_sync(0xffffffffu, sum, o);
    if ((threadIdx.x & 31) == 0) red[threadIdx.x >> 5] = sum;
    __syncthreads();
    float ts = red[0];
    #pragma unroll
    for (int w = 1; w < 8; w++) ts += red[w];
    float inv = 1.0f / ts;

    #pragma unroll
    for (int i = 0; i < 8; i++) {
        int j2 = threadIdx.x + i * 256;
        int j  = 2 * j2;
        if (j < cp)
            p[j2] = pack_h(v[i].x * inv, v[i].y * inv);
    }
}

// ============================================================================
// launch
// ============================================================================
extern "C" void kernel_launch(void* const* d_in, const int* in_sizes, int n_in,
                              void* d_out, int out_size)
{
    const float* prototype = (const float*)d_in[0];
    const float* q_x       = (const float*)d_in[1];
    const int*   mask      = (const int*)  d_in[2];
    const float* Wq        = (const float*)d_in[3];
    const float* Wk        = (const float*)d_in[4];
    const float* Wv        = (const float*)d_in[5];
    const float* Wproj     = (const float*)d_in[6];
    float* out = (float*)d_out;

    __half *ph, *pl, *xh, *wqth, *wqtl, *wkth, *wktl, *wvth, *wvtl,
           *wph, *wpl, *gth, *hth, *qh, *uth, *aph;
    int *idx, *cnt, *cntp;
    cudaGetSymbolAddress((void**)&ph,   s_ph);   cudaGetSymbolAddress((void**)&pl,   s_pl);
    cudaGetSymbolAddress((void**)&xh,   s_xh);
    cudaGetSymbolAddress((void**)&wqth, s_wqth); cudaGetSymbolAddress((void**)&wqtl, s_wqtl);
    cudaGetSymbolAddress((void**)&wkth, s_wkth); cudaGetSymbolAddress((void**)&wktl, s_wktl);
    cudaGetSymbolAddress((void**)&wvth, s_wvth); cudaGetSymbolAddress((void**)&wvtl, s_wvtl);
    cudaGetSymbolAddress((void**)&wph,  s_wph);  cudaGetSymbolAddress((void**)&wpl,  s_wpl);
    cudaGetSymbolAddress((void**)&gth,  s_gth);
    cudaGetSymbolAddress((void**)&hth,  s_hth);
    cudaGetSymbolAddress((void**)&qh,   s_qh);
    cudaGetSymbolAddress((void**)&uth,  s_uth);
    cudaGetSymbolAddress((void**)&aph,  s_aph);
    cudaGetSymbolAddress((void**)&idx,  g_idx);
    cudaGetSymbolAddress((void**)&cnt,  g_cnt);
    cudaGetSymbolAddress((void**)&cntp, g_cntp);

    cudaFuncSetAttribute(gemm_1mma,
                         cudaFuncAttributeMaxDynamicSharedMemorySize, SMEM_1MMA3);
    cudaFuncSetAttribute(fold2_kernel,
                         cudaFuncAttributeMaxDynamicSharedMemorySize, SMEM_AB2);
    cudaFuncSetAttribute(qu_kernel,
                         cudaFuncAttributeMaxDynamicSharedMemorySize, SMEM_AS2);

    const float scale = 0.04419417382415922f;  // 1/sqrt(512)
    dim3 blk(128);

    // mask scan + gather of kept q_x rows (single fp16)
    mask_scan_kernel<<<BATCH, 1024>>>(mask, idx, cnt, cntp);
    gather_h_kernel<<<dim3(NKV, BATCH), 128>>>(q_x, idx, cnt, cntp, xh);

    // splits: prototype + Wproj in one launch; Wq/Wk/Wv transposed
    {
        const int n4a = BATCH * NQ * DIM / 4;
        const int n4b = DIM * DIM / 4;
        split2_kernel<<<(n4a + n4b + 255) / 256, 256>>>(
            prototype, ph, pl, n4a, Wproj, wph, wpl, n4b);
    }
    transpose_split3_kernel<<<dim3(16, 16, 3), dim3(32, 32)>>>(
        Wq, Wk, Wv, wqth, wqtl, wkth, wktl, wvth, wvtl);

    // both weight folds in one launch
    fold2_kernel<<<dim3(DIM/128, DIM/128, 2), blk, SMEM_AB2>>>(
        wkth, wktl, wqth, wqtl, gth,
        wph,  wpl,  wvth, wvtl, hth);

    // merged: q' (proto.Gt^T, 2-stage AS) and uT (Ht.xc^T, 3-stage 1-MMA)
    qu_kernel<<<1280, blk, SMEM_AS2>>>(ph, pl, gth, qh, hth, xh, uth, cntp);

    // logits[b] = scale * q' @ xc^T : 1-MMA 3-stage -> fp16 (in aph)
    gemm_1mma<<<dim3(NKV/128, NQ/128, BATCH), blk, SMEM_1MMA3>>>(
        qh, xh, nullptr, aph,
        NKV, DIM, DIM, DIM,
        (size_t)NQ*DIM, (size_t)NKV*DIM, (size_t)NQ*NKV, scale,
        cntp, nullptr);

    // softmax in place on fp16 logits -> fp16 probs
    softmax_h_kernel<<<BATCH*NQ, 256>>>(aph, cnt, cntp);

    // out[b] = P @ uT^T : 1-MMA 3-stage -> fp32
    gemm_1mma<<<dim3(DIM/128, NQ/128, BATCH), blk, SMEM_1MMA3>>>(
        aph, uth, out, nullptr,
        DIM, NKV, NKV, NKV,
        (size_t)NQ*NKV, (size_t)DIM*NKV, (size_t)NQ*DIM, 1.0f,
        nullptr, cntp);
}